// round 1
// baseline (speedup 1.0000x reference)
#include <cuda_runtime.h>
#include <math.h>

// Problem constants
#define L_SEQ   2048
#define DMODEL  256
#define BATCH   4
#define MFEAT   256
#define NROWS   (BATCH * L_SEQ)   // 8192

// ---------------------------------------------------------------------------
// Scratch: one big __device__ array, constexpr offsets (floats)
// ---------------------------------------------------------------------------
static constexpr long SZ_BIG    = (long)NROWS * DMODEL;     // 2,097,152
static constexpr long OFF_Q     = 0;
static constexpr long OFF_K     = OFF_Q  + SZ_BIG;
static constexpr long OFF_V     = OFF_K  + SZ_BIG;
static constexpr long OFF_XQ    = OFF_V  + SZ_BIG;
static constexpr long OFF_XK    = OFF_XQ + SZ_BIG;
static constexpr long OFF_QP    = OFF_XK + SZ_BIG;
static constexpr long OFF_KP    = OFF_QP + SZ_BIG;
static constexpr long OFF_CTX   = OFF_KP + SZ_BIG;
static constexpr long OFF_KVS   = OFF_CTX + SZ_BIG;                       // 4*256*256
static constexpr long OFF_KSUMP = OFF_KVS + (long)BATCH * MFEAT * DMODEL; // 4*8*256
static constexpr long OFF_DEN   = OFF_KSUMP + (long)BATCH * 8 * MFEAT;   // 8192
static constexpr long OFF_KMAX  = OFF_DEN + NROWS;                        // 4 (as uint)
static constexpr long SCRATCH_TOTAL = OFF_KMAX + 16;

__device__ float g_scratch[SCRATCH_TOTAL];

// ---------------------------------------------------------------------------
// Ordered-uint encoding for deterministic float max via atomicMax
// ---------------------------------------------------------------------------
__device__ __forceinline__ unsigned ord_enc(float f) {
    unsigned u = __float_as_uint(f);
    return (u & 0x80000000u) ? ~u : (u | 0x80000000u);
}
__device__ __forceinline__ float ord_dec(unsigned u) {
    return __uint_as_float((u & 0x80000000u) ? (u & 0x7fffffffu) : ~u);
}

// ---------------------------------------------------------------------------
// Generic tiled SGEMM: C[Md,Nd] = op(A) @ op(B) (+ epilogue)
//   BM=BN=64, BK=16, 256 threads, 4x4 register tile per thread.
//   TRANSA=false: A stored [Md,Kd] row-major. true: A stored [Kd,Md] (A^T access).
//   TRANSB=false: B stored [Kd,Nd].           true: B stored [Nd,Kd].
//   EPI: 0=none  1=+bias[n]  2=+bias, rotary(pos)+0.25 scale  3=C/rowdiv[m]
//   All dims assumed multiples of 64 (true for this problem).
// ---------------------------------------------------------------------------
template <bool TRANSA, bool TRANSB, int EPI>
__global__ __launch_bounds__(256)
void sgemm64(const float* __restrict__ A, const float* __restrict__ B,
             float* __restrict__ C, int Md, int Nd, int Kd,
             const float* __restrict__ bias,
             const float* __restrict__ rowdiv,
             const float* __restrict__ pos,
             long sA, long sB, long sC, long sAux)
{
    const int bz = blockIdx.z;
    A += (long)bz * sA;
    B += (long)bz * sB;
    C += (long)bz * sC;
    if (EPI == 3) rowdiv += (long)bz * sAux;

    __shared__ float As[16][64];
    __shared__ float Bs[16][64];

    const int tid = threadIdx.x;
    const int m0 = blockIdx.y * 64;
    const int n0 = blockIdx.x * 64;
    const int ty = tid >> 4;   // 0..15
    const int tx = tid & 15;   // 0..15

    float acc[4][4] = {};

    for (int k0 = 0; k0 < Kd; k0 += 16) {
        // --- load A tile into As[k][m] ---
        if (!TRANSA) {
            int r  = tid >> 2;     // m within tile, 0..63
            int kq = tid & 3;      // k quad
            float4 f = *(const float4*)&A[(long)(m0 + r) * Kd + k0 + kq * 4];
            As[kq * 4 + 0][r] = f.x;
            As[kq * 4 + 1][r] = f.y;
            As[kq * 4 + 2][r] = f.z;
            As[kq * 4 + 3][r] = f.w;
        } else {
            int r = tid >> 4;      // k within tile, 0..15
            int c = tid & 15;      // m quad
            float4 f = *(const float4*)&A[(long)(k0 + r) * Md + m0 + c * 4];
            *(float4*)&As[r][c * 4] = f;
        }
        // --- load B tile into Bs[k][n] ---
        if (!TRANSB) {
            int r = tid >> 4;
            int c = tid & 15;
            float4 f = *(const float4*)&B[(long)(k0 + r) * Nd + n0 + c * 4];
            *(float4*)&Bs[r][c * 4] = f;
        } else {
            int r  = tid >> 2;     // n within tile
            int kq = tid & 3;
            float4 f = *(const float4*)&B[(long)(n0 + r) * Kd + k0 + kq * 4];
            Bs[kq * 4 + 0][r] = f.x;
            Bs[kq * 4 + 1][r] = f.y;
            Bs[kq * 4 + 2][r] = f.z;
            Bs[kq * 4 + 3][r] = f.w;
        }
        __syncthreads();

        #pragma unroll
        for (int k = 0; k < 16; k++) {
            float a[4], b[4];
            #pragma unroll
            for (int i = 0; i < 4; i++) a[i] = As[k][ty * 4 + i];
            #pragma unroll
            for (int j = 0; j < 4; j++) b[j] = Bs[k][tx * 4 + j];
            #pragma unroll
            for (int i = 0; i < 4; i++)
                #pragma unroll
                for (int j = 0; j < 4; j++)
                    acc[i][j] += a[i] * b[j];
        }
        __syncthreads();
    }

    // --- epilogue + store ---
    #pragma unroll
    for (int i = 0; i < 4; i++) {
        const int m = m0 + ty * 4 + i;
        const int n = n0 + tx * 4;
        float v0 = acc[i][0], v1 = acc[i][1], v2 = acc[i][2], v3 = acc[i][3];
        if (EPI == 1 || EPI == 2) {
            v0 += bias[n];     v1 += bias[n + 1];
            v2 += bias[n + 2]; v3 += bias[n + 3];
        }
        if (EPI == 2) {
            // rotary: r[2i] = x[2i]*cos - x[2i+1]*sin ; r[2i+1] = x[2i+1]*cos + x[2i]*sin
            // cos[l,n] = pos[l, 2*(n/2)+1], sin[l,n] = pos[l, 2*(n/2)]
            const int l = m & (L_SEQ - 1);
            const float* pr = pos + (long)l * DMODEL + n;
            float s0 = pr[0], c0 = pr[1], s1 = pr[2], c1 = pr[3];
            float r0 = v0 * c0 - v1 * s0;
            float r1 = v1 * c0 + v0 * s0;
            float r2 = v2 * c1 - v3 * s1;
            float r3 = v3 * c1 + v2 * s1;
            v0 = r0 * 0.25f; v1 = r1 * 0.25f; v2 = r2 * 0.25f; v3 = r3 * 0.25f;
        }
        if (EPI == 3) {
            float inv = 1.0f / rowdiv[m];
            v0 *= inv; v1 *= inv; v2 *= inv; v3 *= inv;
        }
        float4 out = make_float4(v0, v1, v2, v3);
        *(float4*)&C[(long)m * Nd + n] = out;
    }
}

// ---------------------------------------------------------------------------
// clear: zero kmax slots (ordered-uint identity = 0)
// ---------------------------------------------------------------------------
__global__ void clear_kernel() {
    if (threadIdx.x < BATCH)
        ((unsigned*)(g_scratch + OFF_KMAX))[threadIdx.x] = 0u;
}

// ---------------------------------------------------------------------------
// qp: per row — diag = 0.5*||qs||^2, mx = max_m xp, qp = (1/16)(exp(xp-diag-mx)+eps)
// ---------------------------------------------------------------------------
__global__ __launch_bounds__(256) void qp_kernel() {
    const int row = blockIdx.x;
    const int t   = threadIdx.x;
    const long base = (long)row * MFEAT;

    float x  = g_scratch[OFF_Q  + base + t];
    float xp = g_scratch[OFF_XQ + base + t];

    __shared__ float sm[256];
    sm[t] = x * x;
    __syncthreads();
    for (int s = 128; s; s >>= 1) { if (t < s) sm[t] += sm[t + s]; __syncthreads(); }
    const float diag = 0.5f * sm[0];
    __syncthreads();
    sm[t] = xp;
    __syncthreads();
    for (int s = 128; s; s >>= 1) { if (t < s) sm[t] = fmaxf(sm[t], sm[t + s]); __syncthreads(); }
    const float mx = sm[0];

    g_scratch[OFF_QP + base + t] = 0.0625f * (expf(xp - diag - mx) + 1e-6f);
}

// ---------------------------------------------------------------------------
// kmax: per-batch max over [L,M] via block reduce + deterministic atomicMax
// ---------------------------------------------------------------------------
__global__ __launch_bounds__(256) void kmax_kernel() {
    const int b = blockIdx.y;
    const float* base = g_scratch + OFF_XK + (long)b * L_SEQ * MFEAT;
    const int n = L_SEQ * MFEAT;
    float mx = -3.402823466e38f;
    for (int i = blockIdx.x * blockDim.x + threadIdx.x; i < n; i += gridDim.x * blockDim.x)
        mx = fmaxf(mx, base[i]);
    __shared__ float sm[256];
    const int t = threadIdx.x;
    sm[t] = mx;
    __syncthreads();
    for (int s = 128; s; s >>= 1) { if (t < s) sm[t] = fmaxf(sm[t], sm[t + s]); __syncthreads(); }
    if (t == 0)
        atomicMax((unsigned*)(g_scratch + OFF_KMAX) + b, ord_enc(sm[0]));
}

// ---------------------------------------------------------------------------
// kp: per row — diag from ks row, per-batch mx, kp = (1/16)(exp(xp-diag-mx)+eps)
// ---------------------------------------------------------------------------
__global__ __launch_bounds__(256) void kp_kernel() {
    const int row = blockIdx.x;
    const int b   = row >> 11;  // / L_SEQ
    const int t   = threadIdx.x;
    const long base = (long)row * MFEAT;

    float x  = g_scratch[OFF_K  + base + t];
    float xp = g_scratch[OFF_XK + base + t];

    __shared__ float sm[256];
    sm[t] = x * x;
    __syncthreads();
    for (int s = 128; s; s >>= 1) { if (t < s) sm[t] += sm[t + s]; __syncthreads(); }
    const float diag = 0.5f * sm[0];

    const unsigned u = ((const unsigned*)(g_scratch + OFF_KMAX))[b];
    const float mx = ord_dec(u);

    g_scratch[OFF_KP + base + t] = 0.0625f * (expf(xp - diag - mx) + 1e-6f);
}

// ---------------------------------------------------------------------------
// ksum partials: deterministic two-stage column sum of kp over L
//   stage 1: grid (8, B) — each block sums 256 rows into a partial
// ---------------------------------------------------------------------------
__global__ __launch_bounds__(256) void ksump_kernel() {
    const int b = blockIdx.y, chunk = blockIdx.x, m = threadIdx.x;
    const float* base = g_scratch + OFF_KP + (long)b * L_SEQ * MFEAT;
    float s = 0.f;
    const int r0 = chunk * 256;
    for (int r = 0; r < 256; r++)
        s += base[(long)(r0 + r) * MFEAT + m];
    g_scratch[OFF_KSUMP + ((long)b * 8 + chunk) * MFEAT + m] = s;
}

// ---------------------------------------------------------------------------
// den: den[row] = sum_m qp[row,m] * ksum[b,m]  (ksum folded from 8 partials)
// ---------------------------------------------------------------------------
__global__ __launch_bounds__(256) void den_kernel() {
    const int row = blockIdx.x;
    const int b   = row >> 11;
    const int t   = threadIdx.x;
    float ks = 0.f;
    #pragma unroll
    for (int c = 0; c < 8; c++)
        ks += g_scratch[OFF_KSUMP + ((long)b * 8 + c) * MFEAT + t];
    float v = g_scratch[OFF_QP + (long)row * MFEAT + t] * ks;
    __shared__ float sm[256];
    sm[t] = v;
    __syncthreads();
    for (int s = 128; s; s >>= 1) { if (t < s) sm[t] += sm[t + s]; __syncthreads(); }
    if (t == 0) g_scratch[OFF_DEN + row] = sm[0];
}

// ---------------------------------------------------------------------------
// launch
// ---------------------------------------------------------------------------
extern "C" void kernel_launch(void* const* d_in, const int* in_sizes, int n_in,
                              void* d_out, int out_size)
{
    const float* query = (const float*)d_in[0];
    const float* key   = (const float*)d_in[1];
    const float* value = (const float*)d_in[2];
    // d_in[3] = mask, unused by the reference
    const float* Wq = (const float*)d_in[4];
    const float* bq = (const float*)d_in[5];
    const float* Wk = (const float*)d_in[6];
    const float* bk = (const float*)d_in[7];
    const float* Wv = (const float*)d_in[8];
    const float* bv = (const float*)d_in[9];
    const float* Wo = (const float*)d_in[10];
    const float* bo = (const float*)d_in[11];
    const float* proj = (const float*)d_in[12];
    const float* pos  = (const float*)d_in[13];
    float* out = (float*)d_out;

    void* sp = nullptr;
    cudaGetSymbolAddress(&sp, g_scratch);
    float* S = (float*)sp;

    clear_kernel<<<1, 32>>>();

    // q/k/v projections: [8192,256] @ [256,256] (+bias); q,k get rotary+scale
    dim3 gBig(DMODEL / 64, NROWS / 64);  // (4, 128)
    sgemm64<false, false, 2><<<gBig, 256>>>(query, Wq, S + OFF_Q, NROWS, DMODEL, DMODEL,
                                            bq, nullptr, pos, 0, 0, 0, 0);
    sgemm64<false, false, 2><<<gBig, 256>>>(key, Wk, S + OFF_K, NROWS, DMODEL, DMODEL,
                                            bk, nullptr, pos, 0, 0, 0, 0);
    sgemm64<false, false, 1><<<gBig, 256>>>(value, Wv, S + OFF_V, NROWS, DMODEL, DMODEL,
                                            bv, nullptr, nullptr, 0, 0, 0, 0);

    // xp = qs @ proj^T (proj stored [M,D] -> TRANSB)
    sgemm64<false, true, 0><<<gBig, 256>>>(S + OFF_Q, proj, S + OFF_XQ, NROWS, MFEAT, DMODEL,
                                           nullptr, nullptr, nullptr, 0, 0, 0, 0);
    sgemm64<false, true, 0><<<gBig, 256>>>(S + OFF_K, proj, S + OFF_XK, NROWS, MFEAT, DMODEL,
                                           nullptr, nullptr, nullptr, 0, 0, 0, 0);

    qp_kernel<<<NROWS, 256>>>();
    kmax_kernel<<<dim3(64, BATCH), 256>>>();
    kp_kernel<<<NROWS, 256>>>();
    ksump_kernel<<<dim3(8, BATCH), 256>>>();

    // kvs[b] = kp[b]^T @ v[b] : [256,2048] x [2048,256] (TRANSA, batched)
    dim3 gKVS(DMODEL / 64, MFEAT / 64, BATCH);  // (4, 4, 4)
    sgemm64<true, false, 0><<<gKVS, 256>>>(S + OFF_KP, S + OFF_V, S + OFF_KVS,
                                           MFEAT, DMODEL, L_SEQ,
                                           nullptr, nullptr, nullptr,
                                           (long)L_SEQ * MFEAT, (long)L_SEQ * DMODEL,
                                           (long)MFEAT * DMODEL, 0);

    den_kernel<<<NROWS, 256>>>();

    // ctx[b] = (qp[b] @ kvs[b]) / den : [2048,256] x [256,256] (batched, rowdiv)
    dim3 gNUM(DMODEL / 64, L_SEQ / 64, BATCH);  // (4, 32, 4)
    sgemm64<false, false, 3><<<gNUM, 256>>>(S + OFF_QP, S + OFF_KVS, S + OFF_CTX,
                                            L_SEQ, DMODEL, MFEAT,
                                            nullptr, S + OFF_DEN, nullptr,
                                            (long)L_SEQ * MFEAT, (long)MFEAT * DMODEL,
                                            (long)L_SEQ * DMODEL, (long)L_SEQ);

    // out = ctx @ Wo + bo
    sgemm64<false, false, 1><<<gBig, 256>>>(S + OFF_CTX, Wo, out, NROWS, DMODEL, DMODEL,
                                            bo, nullptr, nullptr, 0, 0, 0, 0);
}

// round 2
// speedup vs baseline: 1.1500x; 1.1500x over previous
#include <cuda_runtime.h>
#include <math.h>

// Problem constants
#define L_SEQ   2048
#define DMODEL  256
#define BATCH   4
#define MFEAT   256
#define NROWS   (BATCH * L_SEQ)   // 8192

// ---------------------------------------------------------------------------
// Scratch
// ---------------------------------------------------------------------------
static constexpr long SZ_BIG    = (long)NROWS * DMODEL;     // 2,097,152
static constexpr long OFF_Q     = 0;
static constexpr long OFF_K     = OFF_Q  + SZ_BIG;
static constexpr long OFF_V     = OFF_K  + SZ_BIG;
static constexpr long OFF_XQ    = OFF_V  + SZ_BIG;
static constexpr long OFF_XK    = OFF_XQ + SZ_BIG;
static constexpr long OFF_QP    = OFF_XK + SZ_BIG;
static constexpr long OFF_KP    = OFF_QP + SZ_BIG;
static constexpr long OFF_CTX   = OFF_KP + SZ_BIG;
static constexpr long OFF_KVS   = OFF_CTX + SZ_BIG;                       // 4*256*256
static constexpr long OFF_KSUMP = OFF_KVS + (long)BATCH * MFEAT * DMODEL; // 4*8*256
static constexpr long OFF_DEN   = OFF_KSUMP + (long)BATCH * 8 * MFEAT;   // 8192
static constexpr long OFF_KMAX  = OFF_DEN + NROWS;                        // 4 (as uint)
static constexpr long SCRATCH_TOTAL = OFF_KMAX + 16;

__device__ float g_scratch[SCRATCH_TOTAL];

// ---------------------------------------------------------------------------
// Ordered-uint encoding for deterministic float max via atomicMax
// ---------------------------------------------------------------------------
__device__ __forceinline__ unsigned ord_enc(float f) {
    unsigned u = __float_as_uint(f);
    return (u & 0x80000000u) ? ~u : (u | 0x80000000u);
}
__device__ __forceinline__ float ord_dec(unsigned u) {
    return __uint_as_float((u & 0x80000000u) ? (u & 0x7fffffffu) : ~u);
}

// ---------------------------------------------------------------------------
// Block reductions over 256 threads (8 warps), shuffle + smem, deterministic
// ---------------------------------------------------------------------------
__device__ __forceinline__ float blockSum256(float v, float* sm8) {
    #pragma unroll
    for (int o = 16; o; o >>= 1) v += __shfl_xor_sync(0xffffffffu, v, o);
    if ((threadIdx.x & 31) == 0) sm8[threadIdx.x >> 5] = v;
    __syncthreads();
    float s = 0.f;
    #pragma unroll
    for (int i = 0; i < 8; i++) s += sm8[i];
    __syncthreads();
    return s;
}
__device__ __forceinline__ float blockMax256(float v, float* sm8) {
    #pragma unroll
    for (int o = 16; o; o >>= 1) v = fmaxf(v, __shfl_xor_sync(0xffffffffu, v, o));
    if ((threadIdx.x & 31) == 0) sm8[threadIdx.x >> 5] = v;
    __syncthreads();
    float s = sm8[0];
    #pragma unroll
    for (int i = 1; i < 8; i++) s = fmaxf(s, sm8[i]);
    __syncthreads();
    return s;
}

// ---------------------------------------------------------------------------
// 128x128x16 double-buffered SGEMM, 256 threads, 8x8 microtile.
//   C[Md,Nd] = A @ op(B) (+ epilogue). A stored [Md,Kd] row-major.
//   TRANSB=false: B stored [Kd,Nd].  true: B stored [Nd,Kd].
//   EPI: 0=none  1=+bias[n]  2=+bias, rotary(pos)+0.25 scale  3=C/rowdiv[m]
//   Md,Nd multiples of 128; Kd multiple of 16.
// ---------------------------------------------------------------------------
template <bool TRANSB, int EPI>
__global__ __launch_bounds__(256)
void sgemm128(const float* __restrict__ A, const float* __restrict__ B,
              float* __restrict__ C, int Md, int Nd, int Kd,
              const float* __restrict__ bias,
              const float* __restrict__ rowdiv,
              const float* __restrict__ pos,
              long sA, long sB, long sC, long sAux)
{
    const int bz = blockIdx.z;
    A += (long)bz * sA;
    B += (long)bz * sB;
    C += (long)bz * sC;
    if (EPI == 3) rowdiv += (long)bz * sAux;

    __shared__ float As[2][16][128];
    __shared__ float Bs[2][16][128];

    const int tid = threadIdx.x;
    const int m0 = blockIdx.y * 128;
    const int n0 = blockIdx.x * 128;
    const int ty8 = (tid >> 4) * 8;
    const int tx8 = (tid & 15) * 8;

    // A-load indices: 128x16 tile, 2 float4 per thread along K
    const int ar  = tid & 127;
    const int akq = tid >> 7;           // 0..1
    // B-load indices
    const int bkr = tid >> 5;           // 0..7   (non-trans)
    const int bcq = tid & 31;           // 0..31
    const int bn  = tid >> 1;           // 0..127 (trans)
    const int bkq = tid & 1;            // 0..1

    float4 av[2], bv[2];

    auto loadA = [&](int k0) {
        #pragma unroll
        for (int t = 0; t < 2; t++)
            av[t] = *(const float4*)&A[(long)(m0 + ar) * Kd + k0 + (akq + 2 * t) * 4];
    };
    auto loadB = [&](int k0) {
        if (!TRANSB) {
            #pragma unroll
            for (int t = 0; t < 2; t++)
                bv[t] = *(const float4*)&B[(long)(k0 + bkr + 8 * t) * Nd + n0 + bcq * 4];
        } else {
            #pragma unroll
            for (int t = 0; t < 2; t++)
                bv[t] = *(const float4*)&B[(long)(n0 + bn) * Kd + k0 + (bkq + 2 * t) * 4];
        }
    };
    auto storeAB = [&](int buf) {
        #pragma unroll
        for (int t = 0; t < 2; t++) {
            int kq = (akq + 2 * t) * 4;
            As[buf][kq + 0][ar] = av[t].x;
            As[buf][kq + 1][ar] = av[t].y;
            As[buf][kq + 2][ar] = av[t].z;
            As[buf][kq + 3][ar] = av[t].w;
        }
        if (!TRANSB) {
            #pragma unroll
            for (int t = 0; t < 2; t++)
                *(float4*)&Bs[buf][bkr + 8 * t][bcq * 4] = bv[t];
        } else {
            #pragma unroll
            for (int t = 0; t < 2; t++) {
                int kq = (bkq + 2 * t) * 4;
                Bs[buf][kq + 0][bn] = bv[t].x;
                Bs[buf][kq + 1][bn] = bv[t].y;
                Bs[buf][kq + 2][bn] = bv[t].z;
                Bs[buf][kq + 3][bn] = bv[t].w;
            }
        }
    };

    float acc[8][8] = {};

    const int nk = Kd >> 4;
    loadA(0); loadB(0);
    storeAB(0);
    __syncthreads();

    int buf = 0;
    for (int t = 0; t < nk; t++) {
        if (t + 1 < nk) { loadA((t + 1) << 4); loadB((t + 1) << 4); }

        #pragma unroll
        for (int k = 0; k < 16; k++) {
            float a[8], b[8];
            *(float4*)&a[0] = *(const float4*)&As[buf][k][ty8];
            *(float4*)&a[4] = *(const float4*)&As[buf][k][ty8 + 4];
            *(float4*)&b[0] = *(const float4*)&Bs[buf][k][tx8];
            *(float4*)&b[4] = *(const float4*)&Bs[buf][k][tx8 + 4];
            #pragma unroll
            for (int i = 0; i < 8; i++)
                #pragma unroll
                for (int j = 0; j < 8; j++)
                    acc[i][j] += a[i] * b[j];
        }

        if (t + 1 < nk) {
            storeAB(buf ^ 1);
            __syncthreads();
        }
        buf ^= 1;
    }

    // --- epilogue + store ---
    #pragma unroll
    for (int i = 0; i < 8; i++) {
        const int m = m0 + ty8 + i;
        float invd;
        if (EPI == 3) invd = 1.0f / rowdiv[m];
        #pragma unroll
        for (int g = 0; g < 8; g += 4) {
            const int n = n0 + tx8 + g;
            float v0 = acc[i][g], v1 = acc[i][g + 1], v2 = acc[i][g + 2], v3 = acc[i][g + 3];
            if (EPI == 1 || EPI == 2) {
                v0 += bias[n];     v1 += bias[n + 1];
                v2 += bias[n + 2]; v3 += bias[n + 3];
            }
            if (EPI == 2) {
                const int l = m & (L_SEQ - 1);
                const float* pr = pos + (long)l * DMODEL + n;
                float s0 = pr[0], c0 = pr[1], s1 = pr[2], c1 = pr[3];
                float r0 = v0 * c0 - v1 * s0;
                float r1 = v1 * c0 + v0 * s0;
                float r2 = v2 * c1 - v3 * s1;
                float r3 = v3 * c1 + v2 * s1;
                v0 = r0 * 0.25f; v1 = r1 * 0.25f; v2 = r2 * 0.25f; v3 = r3 * 0.25f;
            }
            if (EPI == 3) { v0 *= invd; v1 *= invd; v2 *= invd; v3 *= invd; }
            *(float4*)&C[(long)m * Nd + n] = make_float4(v0, v1, v2, v3);
        }
    }
}

// ---------------------------------------------------------------------------
// 64x64x16 SGEMM (kept for kvs: A^T access, small output grid)
// ---------------------------------------------------------------------------
__global__ __launch_bounds__(256)
void sgemm64_tn(const float* __restrict__ A, const float* __restrict__ B,
                float* __restrict__ C, int Md, int Nd, int Kd,
                long sA, long sB, long sC)
{
    const int bz = blockIdx.z;
    A += (long)bz * sA;
    B += (long)bz * sB;
    C += (long)bz * sC;

    __shared__ float As[16][64];
    __shared__ float Bs[16][64];

    const int tid = threadIdx.x;
    const int m0 = blockIdx.y * 64;
    const int n0 = blockIdx.x * 64;
    const int ty = tid >> 4;
    const int tx = tid & 15;

    float acc[4][4] = {};

    for (int k0 = 0; k0 < Kd; k0 += 16) {
        {   // A^T: A stored [Kd, Md]
            int r = tid >> 4;
            int c = tid & 15;
            float4 f = *(const float4*)&A[(long)(k0 + r) * Md + m0 + c * 4];
            *(float4*)&As[r][c * 4] = f;
        }
        {   // B: [Kd, Nd]
            int r = tid >> 4;
            int c = tid & 15;
            float4 f = *(const float4*)&B[(long)(k0 + r) * Nd + n0 + c * 4];
            *(float4*)&Bs[r][c * 4] = f;
        }
        __syncthreads();

        #pragma unroll
        for (int k = 0; k < 16; k++) {
            float a[4], b[4];
            #pragma unroll
            for (int i = 0; i < 4; i++) a[i] = As[k][ty * 4 + i];
            #pragma unroll
            for (int j = 0; j < 4; j++) b[j] = Bs[k][tx * 4 + j];
            #pragma unroll
            for (int i = 0; i < 4; i++)
                #pragma unroll
                for (int j = 0; j < 4; j++)
                    acc[i][j] += a[i] * b[j];
        }
        __syncthreads();
    }

    #pragma unroll
    for (int i = 0; i < 4; i++) {
        const int m = m0 + ty * 4 + i;
        const int n = n0 + tx * 4;
        *(float4*)&C[(long)m * Nd + n] =
            make_float4(acc[i][0], acc[i][1], acc[i][2], acc[i][3]);
    }
}

// ---------------------------------------------------------------------------
// clear: zero kmax slots (ordered-uint identity = 0)
// ---------------------------------------------------------------------------
__global__ void clear_kernel() {
    if (threadIdx.x < BATCH)
        ((unsigned*)(g_scratch + OFF_KMAX))[threadIdx.x] = 0u;
}

// ---------------------------------------------------------------------------
// kmax: per-batch max over [L,M] via block reduce + deterministic atomicMax
// ---------------------------------------------------------------------------
__global__ __launch_bounds__(256) void kmax_kernel() {
    const int b = blockIdx.y;
    const float* base = g_scratch + OFF_XK + (long)b * L_SEQ * MFEAT;
    const int n = L_SEQ * MFEAT;
    float mx = -3.402823466e38f;
    for (int i = blockIdx.x * blockDim.x + threadIdx.x; i < n; i += gridDim.x * blockDim.x)
        mx = fmaxf(mx, base[i]);
    __shared__ float sm8[8];
    mx = blockMax256(mx, sm8);
    if (threadIdx.x == 0)
        atomicMax((unsigned*)(g_scratch + OFF_KMAX) + b, ord_enc(mx));
}

// ---------------------------------------------------------------------------
// kp: per row — diag from k row, per-batch mx, kp = (1/16)(exp(xp-diag-mx)+eps)
// ---------------------------------------------------------------------------
__global__ __launch_bounds__(256) void kp_kernel() {
    const int row = blockIdx.x;
    const int b   = row >> 11;
    const int t   = threadIdx.x;
    const long base = (long)row * MFEAT;

    float x  = g_scratch[OFF_K  + base + t];
    float xp = g_scratch[OFF_XK + base + t];

    __shared__ float sm8[8];
    const float diag = 0.5f * blockSum256(x * x, sm8);
    const unsigned u = ((const unsigned*)(g_scratch + OFF_KMAX))[b];
    const float mx = ord_dec(u);

    g_scratch[OFF_KP + base + t] = 0.0625f * (expf(xp - diag - mx) + 1e-6f);
}

// ---------------------------------------------------------------------------
// ksum partials: deterministic two-stage column sum of kp over L
// ---------------------------------------------------------------------------
__global__ __launch_bounds__(256) void ksump_kernel() {
    const int b = blockIdx.y, chunk = blockIdx.x, m = threadIdx.x;
    const float* base = g_scratch + OFF_KP + (long)b * L_SEQ * MFEAT;
    float s = 0.f;
    const int r0 = chunk * 256;
    for (int r = 0; r < 256; r++)
        s += base[(long)(r0 + r) * MFEAT + m];
    g_scratch[OFF_KSUMP + ((long)b * 8 + chunk) * MFEAT + m] = s;
}

// ---------------------------------------------------------------------------
// qp + den fused: per row — qp = (1/16)(exp(xp-diag-mx)+eps); den = qp . ksum
// ---------------------------------------------------------------------------
__global__ __launch_bounds__(256) void qpden_kernel() {
    const int row = blockIdx.x;
    const int b   = row >> 11;
    const int t   = threadIdx.x;
    const long base = (long)row * MFEAT;

    float x  = g_scratch[OFF_Q  + base + t];
    float xp = g_scratch[OFF_XQ + base + t];

    __shared__ float sm8[8];
    const float diag = 0.5f * blockSum256(x * x, sm8);
    const float mx   = blockMax256(xp, sm8);

    const float qp = 0.0625f * (expf(xp - diag - mx) + 1e-6f);
    g_scratch[OFF_QP + base + t] = qp;

    float ks = 0.f;
    #pragma unroll
    for (int c = 0; c < 8; c++)
        ks += g_scratch[OFF_KSUMP + ((long)b * 8 + c) * MFEAT + t];

    const float den = blockSum256(qp * ks, sm8);
    if (t == 0) g_scratch[OFF_DEN + row] = den;
}

// ---------------------------------------------------------------------------
// launch
// ---------------------------------------------------------------------------
extern "C" void kernel_launch(void* const* d_in, const int* in_sizes, int n_in,
                              void* d_out, int out_size)
{
    const float* query = (const float*)d_in[0];
    const float* key   = (const float*)d_in[1];
    const float* value = (const float*)d_in[2];
    // d_in[3] = mask, unused by the reference
    const float* Wq = (const float*)d_in[4];
    const float* bq = (const float*)d_in[5];
    const float* Wk = (const float*)d_in[6];
    const float* bk = (const float*)d_in[7];
    const float* Wv = (const float*)d_in[8];
    const float* bv = (const float*)d_in[9];
    const float* Wo = (const float*)d_in[10];
    const float* bo = (const float*)d_in[11];
    const float* proj = (const float*)d_in[12];
    const float* pos  = (const float*)d_in[13];
    float* out = (float*)d_out;

    void* sp = nullptr;
    cudaGetSymbolAddress(&sp, g_scratch);
    float* S = (float*)sp;

    clear_kernel<<<1, 32>>>();

    // q/k/v projections: [8192,256] @ [256,256] (+bias); q,k get rotary+scale
    dim3 gBig(DMODEL / 128, NROWS / 128);  // (2, 64)
    sgemm128<false, 2><<<gBig, 256>>>(query, Wq, S + OFF_Q, NROWS, DMODEL, DMODEL,
                                      bq, nullptr, pos, 0, 0, 0, 0);
    sgemm128<false, 2><<<gBig, 256>>>(key, Wk, S + OFF_K, NROWS, DMODEL, DMODEL,
                                      bk, nullptr, pos, 0, 0, 0, 0);
    sgemm128<false, 1><<<gBig, 256>>>(value, Wv, S + OFF_V, NROWS, DMODEL, DMODEL,
                                      bv, nullptr, nullptr, 0, 0, 0, 0);

    // xp = qs @ proj^T (proj stored [M,D] -> TRANSB)
    sgemm128<true, 0><<<gBig, 256>>>(S + OFF_Q, proj, S + OFF_XQ, NROWS, MFEAT, DMODEL,
                                     nullptr, nullptr, nullptr, 0, 0, 0, 0);
    sgemm128<true, 0><<<gBig, 256>>>(S + OFF_K, proj, S + OFF_XK, NROWS, MFEAT, DMODEL,
                                     nullptr, nullptr, nullptr, 0, 0, 0, 0);

    kmax_kernel<<<dim3(64, BATCH), 256>>>();
    kp_kernel<<<NROWS, 256>>>();
    ksump_kernel<<<dim3(8, BATCH), 256>>>();
    qpden_kernel<<<NROWS, 256>>>();

    // kvs[b] = kp[b]^T @ v[b] : [256,2048] x [2048,256] (TN, batched)
    dim3 gKVS(DMODEL / 64, MFEAT / 64, BATCH);  // (4, 4, 4)
    sgemm64_tn<<<gKVS, 256>>>(S + OFF_KP, S + OFF_V, S + OFF_KVS,
                              MFEAT, DMODEL, L_SEQ,
                              (long)L_SEQ * MFEAT, (long)L_SEQ * DMODEL,
                              (long)MFEAT * DMODEL);

    // ctx[b] = (qp[b] @ kvs[b]) / den : [2048,256] x [256,256] (batched, rowdiv)
    dim3 gNUM(DMODEL / 128, L_SEQ / 128, BATCH);  // (2, 16, 4)
    sgemm128<false, 3><<<gNUM, 256>>>(S + OFF_QP, S + OFF_KVS, S + OFF_CTX,
                                      L_SEQ, DMODEL, MFEAT,
                                      nullptr, S + OFF_DEN, nullptr,
                                      (long)L_SEQ * MFEAT, (long)MFEAT * DMODEL,
                                      (long)L_SEQ * DMODEL, (long)L_SEQ);

    // out = ctx @ Wo + bo
    sgemm128<false, 1><<<gBig, 256>>>(S + OFF_CTX, Wo, out, NROWS, DMODEL, DMODEL,
                                      bo, nullptr, nullptr, 0, 0, 0, 0);
}

// round 4
// speedup vs baseline: 1.6862x; 1.4662x over previous
#include <cuda_runtime.h>
#include <cuda_bf16.h>
#include <math.h>
#include <stdint.h>

#define L_SEQ   2048
#define DMODEL  256
#define BATCH   4
#define MFEAT   256
#define NROWS   8192

// ===========================================================================
// Scratch
// ===========================================================================
static constexpr long SZB = (long)NROWS * DMODEL;   // 2,097,152

// f32 scratch
static constexpr long F_Q     = 0;
static constexpr long F_K     = F_Q  + SZB;
static constexpr long F_V     = F_K  + SZB;
static constexpr long F_XQ    = F_V  + SZB;
static constexpr long F_XK    = F_XQ + SZB;
static constexpr long F_KP    = F_XK + SZB;
static constexpr long F_PART  = F_KP + SZB;                 // 32 * 65536
static constexpr long F_DEN   = F_PART + SZB;
static constexpr long F_KSUMP = F_DEN + NROWS;
static constexpr long F_KMAX  = F_KSUMP + (long)BATCH * 8 * MFEAT;
static constexpr long F_TOTAL = F_KMAX + 16;
__device__ float g_f[F_TOTAL];

// bf16 scratch
static constexpr long B_QINH = 0;
static constexpr long B_QINL = B_QINH + SZB;
static constexpr long B_KINH = B_QINL + SZB;
static constexpr long B_KINL = B_KINH + SZB;
static constexpr long B_VINH = B_KINL + SZB;
static constexpr long B_VINL = B_VINH + SZB;
static constexpr long B_QSH  = B_VINL + SZB;
static constexpr long B_QSL  = B_QSH + SZB;
static constexpr long B_KSH  = B_QSL + SZB;
static constexpr long B_KSL  = B_KSH + SZB;
static constexpr long B_QPH  = B_KSL + SZB;
static constexpr long B_QPL  = B_QPH + SZB;
static constexpr long B_KPTH = B_QPL + SZB;
static constexpr long B_KPTL = B_KPTH + SZB;
static constexpr long B_VTH  = B_KPTL + SZB;
static constexpr long B_VTL  = B_VTH + SZB;
static constexpr long B_CTXH = B_VTL + SZB;
static constexpr long B_CTXL = B_CTXH + SZB;
static constexpr long SZW    = 65536;
static constexpr long B_KVSTH = B_CTXL + SZB;               // 4*256*256
static constexpr long B_KVSTL = B_KVSTH + 4 * SZW;
static constexpr long B_WQTH = B_KVSTL + 4 * SZW;
static constexpr long B_WQTL = B_WQTH + SZW;
static constexpr long B_WKTH = B_WQTL + SZW;
static constexpr long B_WKTL = B_WKTH + SZW;
static constexpr long B_WVTH = B_WKTL + SZW;
static constexpr long B_WVTL = B_WVTH + SZW;
static constexpr long B_WOTH = B_WVTL + SZW;
static constexpr long B_WOTL = B_WOTH + SZW;
static constexpr long B_PRJH = B_WOTL + SZW;
static constexpr long B_PRJL = B_PRJH + SZW;
static constexpr long B_TOTAL = B_PRJL + SZW;
__device__ __nv_bfloat16 g_b[B_TOTAL];

// ===========================================================================
// Helpers
// ===========================================================================
__device__ __forceinline__ uint32_t smem_u32(const void* p) {
    uint32_t a;
    asm("{ .reg .u64 t; cvta.to.shared.u64 t, %1; cvt.u32.u64 %0, t; }"
        : "=r"(a) : "l"(p));
    return a;
}
__device__ __forceinline__ void ldsm_x4(uint32_t& r0, uint32_t& r1,
                                        uint32_t& r2, uint32_t& r3, uint32_t addr) {
    asm volatile("ldmatrix.sync.aligned.m8n8.x4.shared.b16 {%0,%1,%2,%3}, [%4];"
                 : "=r"(r0), "=r"(r1), "=r"(r2), "=r"(r3) : "r"(addr));
}
__device__ __forceinline__ void mma16816(float* d, const uint32_t* a, const uint32_t* b) {
    asm volatile("mma.sync.aligned.m16n8k16.row.col.f32.bf16.bf16.f32 "
                 "{%0,%1,%2,%3}, {%4,%5,%6,%7}, {%8,%9}, {%0,%1,%2,%3};"
                 : "+f"(d[0]), "+f"(d[1]), "+f"(d[2]), "+f"(d[3])
                 : "r"(a[0]), "r"(a[1]), "r"(a[2]), "r"(a[3]), "r"(b[0]), "r"(b[1]));
}
__device__ __forceinline__ unsigned ord_enc(float f) {
    unsigned u = __float_as_uint(f);
    return (u & 0x80000000u) ? ~u : (u | 0x80000000u);
}
__device__ __forceinline__ float ord_dec(unsigned u) {
    return __uint_as_float((u & 0x80000000u) ? (u & 0x7fffffffu) : ~u);
}
__device__ __forceinline__ float blockSum256(float v, float* sm8) {
    #pragma unroll
    for (int o = 16; o; o >>= 1) v += __shfl_xor_sync(0xffffffffu, v, o);
    if ((threadIdx.x & 31) == 0) sm8[threadIdx.x >> 5] = v;
    __syncthreads();
    float s = 0.f;
    #pragma unroll
    for (int i = 0; i < 8; i++) s += sm8[i];
    __syncthreads();
    return s;
}
__device__ __forceinline__ float blockMax256(float v, float* sm8) {
    #pragma unroll
    for (int o = 16; o; o >>= 1) v = fmaxf(v, __shfl_xor_sync(0xffffffffu, v, o));
    if ((threadIdx.x & 31) == 0) sm8[threadIdx.x >> 5] = v;
    __syncthreads();
    float s = sm8[0];
    #pragma unroll
    for (int i = 1; i < 8; i++) s = fmaxf(s, sm8[i]);
    __syncthreads();
    return s;
}

// ===========================================================================
// Warp-MMA GEMM: C = (Ah+Al) @ (Bh+Bl)^T-as-[N,K]  (bf16 3-pass split, fp32 acc)
//   Tile 128x128; 8 warps (4M x 2N), warp tile 32x64; K-chunk 32, dbl-buffered.
//   K fixed = 256 per pass (24 chunks total across 3 passes).
//   A: [M,K] row-major bf16 (lda); B: [N,K] row-major bf16 (ldb).
//   EPI: 0 none, 1 +bias[n], 2 +bias +rotary(pos)+0.25, 3 /den[m]
// ===========================================================================
template<int EPI, bool WF32, bool WBF16>
__global__ __launch_bounds__(256)
void mma_gemm(const __nv_bfloat16* __restrict__ Ah, const __nv_bfloat16* __restrict__ Al,
              const __nv_bfloat16* __restrict__ Bh, const __nv_bfloat16* __restrict__ Bl,
              float* __restrict__ Cf, __nv_bfloat16* __restrict__ Ch,
              __nv_bfloat16* __restrict__ Cl,
              const float* __restrict__ bias, const float* __restrict__ den,
              const float* __restrict__ pos,
              int lda, int ldb, int ldc, int nsplit,
              long sAb, long sAs, long sBb, long sBs, long sCb, long sCs, long sDen)
{
    // padded stride: 40 halves (80 B) per row -> conflict-free LDSM
    __shared__ __align__(16) __nv_bfloat16 sA[2][128 * 40];
    __shared__ __align__(16) __nv_bfloat16 sB[2][128 * 40];

    const int tid  = threadIdx.x;
    const int wid  = tid >> 5;
    const int lane = tid & 31;
    const int warp_m = (wid >> 1) * 32;
    const int warp_n = (wid & 1) * 64;

    const int z  = blockIdx.z;
    const int bz = z / nsplit, sp = z % nsplit;
    const long aoff = (long)bz * sAb + (long)sp * sAs;
    const long boff = (long)bz * sBb + (long)sp * sBs;
    const long coff = (long)bz * sCb + (long)sp * sCs;
    Ah += aoff; Al += aoff;
    Bh += boff; Bl += boff;
    if (WF32)  Cf += coff;
    if (WBF16) { Ch += coff; Cl += coff; }
    if (EPI == 3) den += (long)bz * sDen;

    const int m0 = blockIdx.y * 128;
    const int n0 = blockIdx.x * 128;

    float acc[2][8][4] = {};
    uint4 ga[2], gb[2];

    // global load slots: thread t handles slots 2t, 2t+1; slot s -> row s>>2, 16B-chunk s&3
    const int r0s = (tid * 2) >> 2;       // same row for both slots? no: s&3 differs
    (void)r0s;

    auto ldglob = [&](int it) {
        const __nv_bfloat16* Ap = ((it >> 3) == 2) ? Al : Ah;
        const __nv_bfloat16* Bq = ((it >> 3) == 1) ? Bl : Bh;
        const int kk = (it & 7) * 32;
        #pragma unroll
        for (int i = 0; i < 2; i++) {
            const int s = tid * 2 + i;
            const int row = s >> 2, c16 = s & 3;
            ga[i] = *(const uint4*)&Ap[(long)(m0 + row) * lda + kk + c16 * 8];
            gb[i] = *(const uint4*)&Bq[(long)(n0 + row) * ldb + kk + c16 * 8];
        }
    };
    auto stsmem = [&](int buf) {
        #pragma unroll
        for (int i = 0; i < 2; i++) {
            const int s = tid * 2 + i;
            const int row = s >> 2, c16 = s & 3;
            *(uint4*)((char*)sA + buf * 10240 + row * 80 + c16 * 16) = ga[i];
            *(uint4*)((char*)sB + buf * 10240 + row * 80 + c16 * 16) = gb[i];
        }
    };

    const uint32_t baseA0 = smem_u32(sA);
    const uint32_t baseB0 = smem_u32(sB);
    // lane-invariant parts of ldmatrix addresses
    const uint32_t aoffl = (warp_m + (lane & 15)) * 80 + (lane >> 4) * 16;
    const uint32_t boffl = (warp_n + (lane & 7) + ((lane >> 4) & 1) * 8) * 80
                         + ((lane >> 3) & 1) * 16;

    auto compute = [&](int buf) {
        const uint32_t bA = baseA0 + buf * 10240;
        const uint32_t bB = baseB0 + buf * 10240;
        #pragma unroll
        for (int k16 = 0; k16 < 2; k16++) {
            uint32_t a[2][4];
            #pragma unroll
            for (int mt = 0; mt < 2; mt++)
                ldsm_x4(a[mt][0], a[mt][1], a[mt][2], a[mt][3],
                        bA + aoffl + mt * 16 * 80 + k16 * 32);
            uint32_t b[4][4];
            #pragma unroll
            for (int nt2 = 0; nt2 < 4; nt2++)
                ldsm_x4(b[nt2][0], b[nt2][1], b[nt2][2], b[nt2][3],
                        bB + boffl + nt2 * 16 * 80 + k16 * 32);
            #pragma unroll
            for (int mt = 0; mt < 2; mt++)
                #pragma unroll
                for (int nt = 0; nt < 8; nt++)
                    mma16816(acc[mt][nt], a[mt], &b[nt >> 1][(nt & 1) * 2]);
        }
    };

    const int NCH = 24;
    ldglob(0); stsmem(0);
    __syncthreads();
    int buf = 0;
    #pragma unroll 1
    for (int it = 0; it < NCH; it++) {
        if (it + 1 < NCH) ldglob(it + 1);
        compute(buf);
        if (it + 1 < NCH) { stsmem(buf ^ 1); __syncthreads(); }
        buf ^= 1;
    }

    // --- epilogue ---
    #pragma unroll
    for (int mt = 0; mt < 2; mt++) {
        #pragma unroll
        for (int hf = 0; hf < 2; hf++) {
            const int m = m0 + warp_m + mt * 16 + (lane >> 2) + hf * 8;
            float invd = 1.0f;
            if (EPI == 3) invd = 1.0f / den[m];
            const int l = m & (L_SEQ - 1);
            #pragma unroll
            for (int nt = 0; nt < 8; nt++) {
                const int n = n0 + warp_n + nt * 8 + (lane & 3) * 2;
                float v0 = acc[mt][nt][hf * 2 + 0];
                float v1 = acc[mt][nt][hf * 2 + 1];
                if (EPI == 1 || EPI == 2) { v0 += bias[n]; v1 += bias[n + 1]; }
                if (EPI == 2) {
                    const float sn = pos[(long)l * DMODEL + n];
                    const float cs = pos[(long)l * DMODEL + n + 1];
                    const float q0 = v0 * cs - v1 * sn;
                    const float q1 = v1 * cs + v0 * sn;
                    v0 = q0 * 0.25f; v1 = q1 * 0.25f;
                }
                if (EPI == 3) { v0 *= invd; v1 *= invd; }
                if (WF32)
                    *(float2*)&Cf[(long)m * ldc + n] = make_float2(v0, v1);
                if (WBF16) {
                    __nv_bfloat16 h0 = __float2bfloat16(v0);
                    __nv_bfloat16 h1 = __float2bfloat16(v1);
                    float l0 = v0 - __bfloat162float(h0);
                    float l1 = v1 - __bfloat162float(h1);
                    unsigned hp = ((unsigned)__bfloat16_as_ushort(h1) << 16)
                                | __bfloat16_as_ushort(h0);
                    unsigned lp = ((unsigned)__bfloat16_as_ushort(__float2bfloat16(l1)) << 16)
                                | __bfloat16_as_ushort(__float2bfloat16(l0));
                    *(unsigned*)&Ch[(long)m * ldc + n] = hp;
                    *(unsigned*)&Cl[(long)m * ldc + n] = lp;
                }
            }
        }
    }
}

// ===========================================================================
// Elementwise / conversion kernels
// ===========================================================================
__global__ void clear_kernel() {
    if (threadIdx.x < BATCH)
        ((unsigned*)(g_f + F_KMAX))[threadIdx.x] = 0u;
}

__global__ __launch_bounds__(256)
void conv_hl(const float* __restrict__ in, __nv_bfloat16* __restrict__ h,
             __nv_bfloat16* __restrict__ l, long n) {
    long i = (long)blockIdx.x * 256 + threadIdx.x;
    if (i < n) {
        float x = in[i];
        __nv_bfloat16 hi = __float2bfloat16(x);
        h[i] = hi;
        l[i] = __float2bfloat16(x - __bfloat162float(hi));
    }
}

// transpose + convert: out[c][r] = in[r][c], f32 -> bf16 hi/lo
__global__ __launch_bounds__(256)
void tconv(const float* __restrict__ in, __nv_bfloat16* __restrict__ oh,
           __nv_bfloat16* __restrict__ ol, int R, int C, long sin, long sout) {
    __shared__ float t[32][33];
    in += (long)blockIdx.z * sin;
    oh += (long)blockIdx.z * sout;
    ol += (long)blockIdx.z * sout;
    const int r0 = blockIdx.x * 32, c0 = blockIdx.y * 32;
    const int tx = threadIdx.x, ty = threadIdx.y;
    #pragma unroll
    for (int d = 0; d < 4; d++)
        t[ty + 8 * d][tx] = in[(long)(r0 + ty + 8 * d) * C + c0 + tx];
    __syncthreads();
    #pragma unroll
    for (int d = 0; d < 4; d++) {
        const int cc = c0 + ty + 8 * d;
        float x = t[tx][ty + 8 * d];
        __nv_bfloat16 hi = __float2bfloat16(x);
        long o = (long)cc * R + r0 + tx;
        oh[o] = hi;
        ol[o] = __float2bfloat16(x - __bfloat162float(hi));
    }
}

// kvs reduce (8 split-K partials) + transpose + convert -> kvsT hi/lo
__global__ __launch_bounds__(256)
void kvsred() {
    __shared__ float t[32][33];
    const int b = blockIdx.z;
    const int m0 = blockIdx.x * 32, d0 = blockIdx.y * 32;
    const int tx = threadIdx.x, ty = threadIdx.y;
    const float* p = g_f + F_PART + (long)b * 8 * SZW;
    #pragma unroll
    for (int dd = 0; dd < 4; dd++) {
        const int m = m0 + ty + 8 * dd;
        float s = 0.f;
        #pragma unroll
        for (int spl = 0; spl < 8; spl++)
            s += p[(long)spl * SZW + (long)m * 256 + d0 + tx];
        t[ty + 8 * dd][tx] = s;
    }
    __syncthreads();
    #pragma unroll
    for (int dd = 0; dd < 4; dd++) {
        const int d = d0 + ty + 8 * dd;
        float x = t[tx][ty + 8 * dd];
        __nv_bfloat16 hi = __float2bfloat16(x);
        long o = (long)b * SZW + (long)d * 256 + m0 + tx;
        g_b[B_KVSTH + o] = hi;
        g_b[B_KVSTL + o] = __float2bfloat16(x - __bfloat162float(hi));
    }
}

__global__ __launch_bounds__(256) void kmax_kernel() {
    const int b = blockIdx.y;
    const float* base = g_f + F_XK + (long)b * L_SEQ * MFEAT;
    const int n = L_SEQ * MFEAT;
    float mx = -3.402823466e38f;
    for (int i = blockIdx.x * blockDim.x + threadIdx.x; i < n; i += gridDim.x * blockDim.x)
        mx = fmaxf(mx, base[i]);
    __shared__ float sm8[8];
    mx = blockMax256(mx, sm8);
    if (threadIdx.x == 0)
        atomicMax((unsigned*)(g_f + F_KMAX) + b, ord_enc(mx));
}

__global__ __launch_bounds__(256) void kp_kernel() {
    const int row = blockIdx.x;
    const int b   = row >> 11;
    const int t   = threadIdx.x;
    const long base = (long)row * MFEAT;
    float x  = g_f[F_K  + base + t];
    float xp = g_f[F_XK + base + t];
    __shared__ float sm8[8];
    const float diag = 0.5f * blockSum256(x * x, sm8);
    const float mx = ord_dec(((const unsigned*)(g_f + F_KMAX))[b]);
    g_f[F_KP + base + t] = 0.0625f * (expf(xp - diag - mx) + 1e-6f);
}

__global__ __launch_bounds__(256) void ksump_kernel() {
    const int b = blockIdx.y, chunk = blockIdx.x, m = threadIdx.x;
    const float* base = g_f + F_KP + (long)b * L_SEQ * MFEAT;
    float s = 0.f;
    const int r0 = chunk * 256;
    for (int r = 0; r < 256; r++)
        s += base[(long)(r0 + r) * MFEAT + m];
    g_f[F_KSUMP + ((long)b * 8 + chunk) * MFEAT + m] = s;
}

// qp (bf16 hi/lo) + den fused
__global__ __launch_bounds__(256) void qpden_kernel() {
    const int row = blockIdx.x;
    const int b   = row >> 11;
    const int t   = threadIdx.x;
    const long base = (long)row * MFEAT;
    float x  = g_f[F_Q  + base + t];
    float xp = g_f[F_XQ + base + t];
    __shared__ float sm8[8];
    const float diag = 0.5f * blockSum256(x * x, sm8);
    const float mx   = blockMax256(xp, sm8);
    const float qp = 0.0625f * (expf(xp - diag - mx) + 1e-6f);
    __nv_bfloat16 hi = __float2bfloat16(qp);
    g_b[B_QPH + base + t] = hi;
    g_b[B_QPL + base + t] = __float2bfloat16(qp - __bfloat162float(hi));
    float ks = 0.f;
    #pragma unroll
    for (int c = 0; c < 8; c++)
        ks += g_f[F_KSUMP + ((long)b * 8 + c) * MFEAT + t];
    const float den = blockSum256(qp * ks, sm8);
    if (t == 0) g_f[F_DEN + row] = den;
}

// ===========================================================================
// launch
// ===========================================================================
extern "C" void kernel_launch(void* const* d_in, const int* in_sizes, int n_in,
                              void* d_out, int out_size)
{
    const float* query = (const float*)d_in[0];
    const float* key   = (const float*)d_in[1];
    const float* value = (const float*)d_in[2];
    const float* Wq = (const float*)d_in[4];
    const float* bq = (const float*)d_in[5];
    const float* Wk = (const float*)d_in[6];
    const float* bk = (const float*)d_in[7];
    const float* Wv = (const float*)d_in[8];
    const float* bv = (const float*)d_in[9];
    const float* Wo = (const float*)d_in[10];
    const float* bo = (const float*)d_in[11];
    const float* proj = (const float*)d_in[12];
    const float* pos  = (const float*)d_in[13];
    float* out = (float*)d_out;

    void* fp = nullptr; cudaGetSymbolAddress(&fp, g_f);
    void* bp = nullptr; cudaGetSymbolAddress(&bp, g_b);
    float* F = (float*)fp;
    __nv_bfloat16* Bp = (__nv_bfloat16*)bp;

    clear_kernel<<<1, 32>>>();

    // input + weight conversions
    conv_hl<<<(int)(SZB / 256), 256>>>(query, Bp + B_QINH, Bp + B_QINL, SZB);
    conv_hl<<<(int)(SZB / 256), 256>>>(key,   Bp + B_KINH, Bp + B_KINL, SZB);
    conv_hl<<<(int)(SZB / 256), 256>>>(value, Bp + B_VINH, Bp + B_VINL, SZB);
    dim3 tb(32, 8);
    tconv<<<dim3(8, 8, 1), tb>>>(Wq, Bp + B_WQTH, Bp + B_WQTL, 256, 256, 0, 0);
    tconv<<<dim3(8, 8, 1), tb>>>(Wk, Bp + B_WKTH, Bp + B_WKTL, 256, 256, 0, 0);
    tconv<<<dim3(8, 8, 1), tb>>>(Wv, Bp + B_WVTH, Bp + B_WVTL, 256, 256, 0, 0);
    tconv<<<dim3(8, 8, 1), tb>>>(Wo, Bp + B_WOTH, Bp + B_WOTL, 256, 256, 0, 0);
    conv_hl<<<256, 256>>>(proj, Bp + B_PRJH, Bp + B_PRJL, SZW);   // proj already [N,K]

    // projections: [8192,256] @ W^T, grid (N/128, M/128)
    dim3 gP(2, 64, 1);
    mma_gemm<2, true, true><<<gP, 256>>>(Bp + B_QINH, Bp + B_QINL, Bp + B_WQTH, Bp + B_WQTL,
        F + F_Q, Bp + B_QSH, Bp + B_QSL, bq, nullptr, pos,
        256, 256, 256, 1, 0, 0, 0, 0, 0, 0, 0);
    mma_gemm<2, true, true><<<gP, 256>>>(Bp + B_KINH, Bp + B_KINL, Bp + B_WKTH, Bp + B_WKTL,
        F + F_K, Bp + B_KSH, Bp + B_KSL, bk, nullptr, pos,
        256, 256, 256, 1, 0, 0, 0, 0, 0, 0, 0);
    mma_gemm<1, true, false><<<gP, 256>>>(Bp + B_VINH, Bp + B_VINL, Bp + B_WVTH, Bp + B_WVTL,
        F + F_V, nullptr, nullptr, bv, nullptr, nullptr,
        256, 256, 256, 1, 0, 0, 0, 0, 0, 0, 0);

    // feature projections: xp = Qs @ proj^T
    mma_gemm<0, true, false><<<gP, 256>>>(Bp + B_QSH, Bp + B_QSL, Bp + B_PRJH, Bp + B_PRJL,
        F + F_XQ, nullptr, nullptr, nullptr, nullptr, nullptr,
        256, 256, 256, 1, 0, 0, 0, 0, 0, 0, 0);
    mma_gemm<0, true, false><<<gP, 256>>>(Bp + B_KSH, Bp + B_KSL, Bp + B_PRJH, Bp + B_PRJL,
        F + F_XK, nullptr, nullptr, nullptr, nullptr, nullptr,
        256, 256, 256, 1, 0, 0, 0, 0, 0, 0, 0);

    // softmax-kernel features
    kmax_kernel<<<dim3(64, BATCH), 256>>>();
    kp_kernel<<<NROWS, 256>>>();
    ksump_kernel<<<dim3(8, BATCH), 256>>>();
    qpden_kernel<<<NROWS, 256>>>();

    // transposes for the TN GEMM operands
    tconv<<<dim3(64, 8, BATCH), tb>>>(F + F_KP, Bp + B_KPTH, Bp + B_KPTL,
                                      L_SEQ, 256, (long)L_SEQ * 256, (long)L_SEQ * 256);
    tconv<<<dim3(64, 8, BATCH), tb>>>(F + F_V, Bp + B_VTH, Bp + B_VTL,
                                      L_SEQ, 256, (long)L_SEQ * 256, (long)L_SEQ * 256);

    // kvs[b] = kp[b]^T @ v[b]  (split-K = 8, z = b*8+s)
    dim3 gKVS(2, 2, 32);
    mma_gemm<0, true, false><<<gKVS, 256>>>(Bp + B_KPTH, Bp + B_KPTL, Bp + B_VTH, Bp + B_VTL,
        F + F_PART, nullptr, nullptr, nullptr, nullptr, nullptr,
        2048, 2048, 256, 8,
        (long)256 * 2048, 256, (long)256 * 2048, 256, (long)8 * SZW, SZW, 0);
    kvsred<<<dim3(8, 8, BATCH), tb>>>();

    // ctx = (qp @ kvs) / den  (batched over z = b)
    dim3 gNUM(2, 16, BATCH);
    mma_gemm<3, false, true><<<gNUM, 256>>>(Bp + B_QPH, Bp + B_QPL, Bp + B_KVSTH, Bp + B_KVSTL,
        nullptr, Bp + B_CTXH, Bp + B_CTXL, nullptr, F + F_DEN, nullptr,
        256, 256, 256, 1,
        (long)L_SEQ * 256, 0, SZW, 0, (long)L_SEQ * 256, 0, L_SEQ);

    // out = ctx @ Wo + bo
    mma_gemm<1, true, false><<<gP, 256>>>(Bp + B_CTXH, Bp + B_CTXL, Bp + B_WOTH, Bp + B_WOTL,
        out, nullptr, nullptr, bo, nullptr, nullptr,
        256, 256, 256, 1, 0, 0, 0, 0, 0, 0, 0);
}

// round 5
// speedup vs baseline: 1.7081x; 1.0130x over previous
#include <cuda_runtime.h>
#include <cuda_bf16.h>
#include <math.h>
#include <stdint.h>

#define L_SEQ   2048
#define DMODEL  256
#define BATCH   4
#define MFEAT   256
#define NROWS   8192

// ===========================================================================
// Scratch
// ===========================================================================
static constexpr long SZB = (long)NROWS * DMODEL;   // 2,097,152
static constexpr long SZW = 65536;

// f32 scratch
static constexpr long F_XQ    = 0;
static constexpr long F_XK    = F_XQ + SZB;
static constexpr long F_PART  = F_XK + SZB;                 // 32 * 65536
static constexpr long F_DEN   = F_PART + SZB;
static constexpr long F_KSUMP = F_DEN + NROWS;
static constexpr long F_KMAX  = F_KSUMP + (long)BATCH * 8 * MFEAT;
static constexpr long F_TOTAL = F_KMAX + 16;
__device__ float g_f[F_TOTAL];

// bf16 scratch
static constexpr long B_QSH  = 0;
static constexpr long B_QSL  = B_QSH + SZB;
static constexpr long B_KSH  = B_QSL + SZB;
static constexpr long B_KSL  = B_KSH + SZB;
static constexpr long B_VH   = B_KSL + SZB;
static constexpr long B_VL   = B_VH  + SZB;
static constexpr long B_QPH  = B_VL  + SZB;
static constexpr long B_QPL  = B_QPH + SZB;
static constexpr long B_KPH  = B_QPL + SZB;
static constexpr long B_KPL  = B_KPH + SZB;
static constexpr long B_CTXH = B_KPL + SZB;
static constexpr long B_CTXL = B_CTXH + SZB;
static constexpr long B_KVSTH = B_CTXL + SZB;               // 4*256*256
static constexpr long B_KVSTL = B_KVSTH + 4 * SZW;
static constexpr long B_WQTH = B_KVSTL + 4 * SZW;
static constexpr long B_WQTL = B_WQTH + SZW;
static constexpr long B_WKTH = B_WQTL + SZW;
static constexpr long B_WKTL = B_WKTH + SZW;
static constexpr long B_WVTH = B_WKTL + SZW;
static constexpr long B_WVTL = B_WVTH + SZW;
static constexpr long B_WOTH = B_WVTL + SZW;
static constexpr long B_WOTL = B_WOTH + SZW;
static constexpr long B_PRJH = B_WOTL + SZW;
static constexpr long B_PRJL = B_PRJH + SZW;
static constexpr long B_TOTAL = B_PRJL + SZW;
__device__ __nv_bfloat16 g_b[B_TOTAL];

// ===========================================================================
// Helpers
// ===========================================================================
__device__ __forceinline__ uint32_t smem_u32(const void* p) {
    uint32_t a;
    asm("{ .reg .u64 t; cvta.to.shared.u64 t, %1; cvt.u32.u64 %0, t; }"
        : "=r"(a) : "l"(p));
    return a;
}
__device__ __forceinline__ void ldsm_x4(uint32_t& r0, uint32_t& r1,
                                        uint32_t& r2, uint32_t& r3, uint32_t addr) {
    asm volatile("ldmatrix.sync.aligned.m8n8.x4.shared.b16 {%0,%1,%2,%3}, [%4];"
                 : "=r"(r0), "=r"(r1), "=r"(r2), "=r"(r3) : "r"(addr));
}
__device__ __forceinline__ void ldsm_x4_t(uint32_t& r0, uint32_t& r1,
                                          uint32_t& r2, uint32_t& r3, uint32_t addr) {
    asm volatile("ldmatrix.sync.aligned.m8n8.x4.trans.shared.b16 {%0,%1,%2,%3}, [%4];"
                 : "=r"(r0), "=r"(r1), "=r"(r2), "=r"(r3) : "r"(addr));
}
__device__ __forceinline__ void mma16816(float* d, const uint32_t* a, const uint32_t* b) {
    asm volatile("mma.sync.aligned.m16n8k16.row.col.f32.bf16.bf16.f32 "
                 "{%0,%1,%2,%3}, {%4,%5,%6,%7}, {%8,%9}, {%0,%1,%2,%3};"
                 : "+f"(d[0]), "+f"(d[1]), "+f"(d[2]), "+f"(d[3])
                 : "r"(a[0]), "r"(a[1]), "r"(a[2]), "r"(a[3]), "r"(b[0]), "r"(b[1]));
}
__device__ __forceinline__ unsigned ord_enc(float f) {
    unsigned u = __float_as_uint(f);
    return (u & 0x80000000u) ? ~u : (u | 0x80000000u);
}
__device__ __forceinline__ float ord_dec(unsigned u) {
    return __uint_as_float((u & 0x80000000u) ? (u & 0x7fffffffu) : ~u);
}
__device__ __forceinline__ float blockSum256(float v, float* sm8) {
    #pragma unroll
    for (int o = 16; o; o >>= 1) v += __shfl_xor_sync(0xffffffffu, v, o);
    if ((threadIdx.x & 31) == 0) sm8[threadIdx.x >> 5] = v;
    __syncthreads();
    float s = 0.f;
    #pragma unroll
    for (int i = 0; i < 8; i++) s += sm8[i];
    __syncthreads();
    return s;
}
__device__ __forceinline__ float blockMax256(float v, float* sm8) {
    #pragma unroll
    for (int o = 16; o; o >>= 1) v = fmaxf(v, __shfl_xor_sync(0xffffffffu, v, o));
    if ((threadIdx.x & 31) == 0) sm8[threadIdx.x >> 5] = v;
    __syncthreads();
    float s = sm8[0];
    #pragma unroll
    for (int i = 1; i < 8; i++) s = fmaxf(s, sm8[i]);
    __syncthreads();
    return s;
}
__device__ __forceinline__ uint4 pack8(const float* x, bool lo_pass) {
    unsigned short h[8];
    #pragma unroll
    for (int j = 0; j < 8; j++) {
        __nv_bfloat16 hi = __float2bfloat16(x[j]);
        h[j] = lo_pass
             ? __bfloat16_as_ushort(__float2bfloat16(x[j] - __bfloat162float(hi)))
             : __bfloat16_as_ushort(hi);
    }
    return make_uint4((unsigned)h[0] | ((unsigned)h[1] << 16),
                      (unsigned)h[2] | ((unsigned)h[3] << 16),
                      (unsigned)h[4] | ((unsigned)h[5] << 16),
                      (unsigned)h[6] | ((unsigned)h[7] << 16));
}

// ===========================================================================
// Warp-MMA GEMM (NT): C = (Ah+Al) @ (Bh+Bl)^T-as-[N,K]  bf16 split, fp32 acc.
//   Tile 128x128; 8 warps (4Mx2N); K-chunk 32, dbl-buffered; K=256, 24 chunks.
//   AF32: A loaded from f32 [M,K] with on-the-fly hi/lo conversion.
//   EPI: 0 none, 1 +bias[n], 2 +bias+rotary+0.25, 3 /den[m]
//   DOMAX: per-batch ordered atomicMax of raw acc into g_f[F_KMAX + m0>>11].
// ===========================================================================
template<int EPI, bool AF32, bool WF32, bool WBF16, bool DOMAX>
__global__ __launch_bounds__(256)
void mma_gemm(const float* __restrict__ Af,
              const __nv_bfloat16* __restrict__ Ah, const __nv_bfloat16* __restrict__ Al,
              const __nv_bfloat16* __restrict__ Bh, const __nv_bfloat16* __restrict__ Bl,
              float* __restrict__ Cf, __nv_bfloat16* __restrict__ Ch,
              __nv_bfloat16* __restrict__ Cl,
              const float* __restrict__ bias, const float* __restrict__ den,
              const float* __restrict__ pos,
              int lda, int ldb, int ldc,
              long sAb, long sBb, long sCb, long sDen)
{
    __shared__ __align__(16) __nv_bfloat16 sA[2][128 * 40];
    __shared__ __align__(16) __nv_bfloat16 sB[2][128 * 40];
    __shared__ float sm8[8];

    const int tid  = threadIdx.x;
    const int wid  = tid >> 5;
    const int lane = tid & 31;
    const int warp_m = (wid >> 1) * 32;
    const int warp_n = (wid & 1) * 64;

    const int bz = blockIdx.z;
    if (AF32) Af += (long)bz * sAb;
    else { Ah += (long)bz * sAb; Al += (long)bz * sAb; }
    Bh += (long)bz * sBb; Bl += (long)bz * sBb;
    if (WF32)  Cf += (long)bz * sCb;
    if (WBF16) { Ch += (long)bz * sCb; Cl += (long)bz * sCb; }
    if (EPI == 3) den += (long)bz * sDen;

    const int m0 = blockIdx.y * 128;
    const int n0 = blockIdx.x * 128;

    float acc[2][8][4] = {};
    uint4 ga[2], gb[2];

    auto ldglob = [&](int it) {
        const int pass = it >> 3;
        const int kk = (it & 7) * 32;
        const __nv_bfloat16* Bq = (pass == 1) ? Bl : Bh;
        #pragma unroll
        for (int i = 0; i < 2; i++) {
            const int s = tid * 2 + i;
            const int row = s >> 2, c16 = s & 3;
            if (AF32) {
                float4 f0 = *(const float4*)&Af[(long)(m0 + row) * lda + kk + c16 * 8];
                float4 f1 = *(const float4*)&Af[(long)(m0 + row) * lda + kk + c16 * 8 + 4];
                float x[8] = {f0.x, f0.y, f0.z, f0.w, f1.x, f1.y, f1.z, f1.w};
                ga[i] = pack8(x, pass == 2);
            } else {
                const __nv_bfloat16* Ap = (pass == 2) ? Al : Ah;
                ga[i] = *(const uint4*)&Ap[(long)(m0 + row) * lda + kk + c16 * 8];
            }
            gb[i] = *(const uint4*)&Bq[(long)(n0 + row) * ldb + kk + c16 * 8];
        }
    };
    auto stsmem = [&](int buf) {
        #pragma unroll
        for (int i = 0; i < 2; i++) {
            const int s = tid * 2 + i;
            const int row = s >> 2, c16 = s & 3;
            *(uint4*)((char*)sA + buf * 10240 + row * 80 + c16 * 16) = ga[i];
            *(uint4*)((char*)sB + buf * 10240 + row * 80 + c16 * 16) = gb[i];
        }
    };

    const uint32_t baseA0 = smem_u32(sA);
    const uint32_t baseB0 = smem_u32(sB);
    const uint32_t aoffl = (warp_m + (lane & 15)) * 80 + (lane >> 4) * 16;
    const uint32_t boffl = (warp_n + (lane & 7) + ((lane >> 4) & 1) * 8) * 80
                         + ((lane >> 3) & 1) * 16;

    auto compute = [&](int buf) {
        const uint32_t bA = baseA0 + buf * 10240;
        const uint32_t bB = baseB0 + buf * 10240;
        #pragma unroll
        for (int k16 = 0; k16 < 2; k16++) {
            uint32_t a[2][4];
            #pragma unroll
            for (int mt = 0; mt < 2; mt++)
                ldsm_x4(a[mt][0], a[mt][1], a[mt][2], a[mt][3],
                        bA + aoffl + mt * 16 * 80 + k16 * 32);
            uint32_t b[4][4];
            #pragma unroll
            for (int nt2 = 0; nt2 < 4; nt2++)
                ldsm_x4(b[nt2][0], b[nt2][1], b[nt2][2], b[nt2][3],
                        bB + boffl + nt2 * 16 * 80 + k16 * 32);
            #pragma unroll
            for (int mt = 0; mt < 2; mt++)
                #pragma unroll
                for (int nt = 0; nt < 8; nt++)
                    mma16816(acc[mt][nt], a[mt], &b[nt >> 1][(nt & 1) * 2]);
        }
    };

    const int NCH = 24;
    ldglob(0); stsmem(0);
    __syncthreads();
    int buf = 0;
    #pragma unroll 1
    for (int it = 0; it < NCH; it++) {
        if (it + 1 < NCH) ldglob(it + 1);
        compute(buf);
        if (it + 1 < NCH) { stsmem(buf ^ 1); __syncthreads(); }
        buf ^= 1;
    }

    if (DOMAX) {
        float mx = -3.402823466e38f;
        #pragma unroll
        for (int mt = 0; mt < 2; mt++)
            #pragma unroll
            for (int nt = 0; nt < 8; nt++)
                #pragma unroll
                for (int q = 0; q < 4; q++)
                    mx = fmaxf(mx, acc[mt][nt][q]);
        __syncthreads();
        mx = blockMax256(mx, sm8);
        if (tid == 0)
            atomicMax((unsigned*)(g_f + F_KMAX) + (m0 >> 11), ord_enc(mx));
    }

    // --- epilogue ---
    #pragma unroll
    for (int mt = 0; mt < 2; mt++) {
        #pragma unroll
        for (int hf = 0; hf < 2; hf++) {
            const int m = m0 + warp_m + mt * 16 + (lane >> 2) + hf * 8;
            float invd = 1.0f;
            if (EPI == 3) invd = 1.0f / den[m];
            const int l = m & (L_SEQ - 1);
            #pragma unroll
            for (int nt = 0; nt < 8; nt++) {
                const int n = n0 + warp_n + nt * 8 + (lane & 3) * 2;
                float v0 = acc[mt][nt][hf * 2 + 0];
                float v1 = acc[mt][nt][hf * 2 + 1];
                if (EPI == 1 || EPI == 2) { v0 += bias[n]; v1 += bias[n + 1]; }
                if (EPI == 2) {
                    const float sn = pos[(long)l * DMODEL + n];
                    const float cs = pos[(long)l * DMODEL + n + 1];
                    const float q0 = v0 * cs - v1 * sn;
                    const float q1 = v1 * cs + v0 * sn;
                    v0 = q0 * 0.25f; v1 = q1 * 0.25f;
                }
                if (EPI == 3) { v0 *= invd; v1 *= invd; }
                if (WF32)
                    *(float2*)&Cf[(long)m * ldc + n] = make_float2(v0, v1);
                if (WBF16) {
                    __nv_bfloat16 h0 = __float2bfloat16(v0);
                    __nv_bfloat16 h1 = __float2bfloat16(v1);
                    float l0 = v0 - __bfloat162float(h0);
                    float l1 = v1 - __bfloat162float(h1);
                    unsigned hp = ((unsigned)__bfloat16_as_ushort(h1) << 16)
                                | __bfloat16_as_ushort(h0);
                    unsigned lp = ((unsigned)__bfloat16_as_ushort(__float2bfloat16(l1)) << 16)
                                | __bfloat16_as_ushort(__float2bfloat16(l0));
                    *(unsigned*)&Ch[(long)m * ldc + n] = hp;
                    *(unsigned*)&Cl[(long)m * ldc + n] = lp;
                }
            }
        }
    }
}

// ===========================================================================
// Warp-MMA GEMM (TN): C[M,N] = (Ah+Al)^T @ (Bh+Bl)
//   A stored [K,M] bf16 hi/lo (kp: [L, MFEAT]); B stored [K,N] (v: [L, D]).
//   Loaded with ldmatrix .trans. Split-K over z: z = bz*8 + sp, 256 K-rows/split.
//   Output f32 partials.
// ===========================================================================
__global__ __launch_bounds__(256)
void mma_gemm_tn(const __nv_bfloat16* __restrict__ Ah, const __nv_bfloat16* __restrict__ Al,
                 const __nv_bfloat16* __restrict__ Bh, const __nv_bfloat16* __restrict__ Bl,
                 float* __restrict__ Cf,
                 int lda, int ldb, int ldc,
                 long sAb, long sAs, long sBb, long sBs, long sCb, long sCs)
{
    // chunk = 32 K-rows x 128 cols; row stride 136 halves (272B, 16B-aligned,
    // 68-word stride -> 8 ldmatrix rows cover all 32 banks exactly once)
    __shared__ __align__(16) __nv_bfloat16 sA[2][32 * 136];
    __shared__ __align__(16) __nv_bfloat16 sB[2][32 * 136];

    const int tid  = threadIdx.x;
    const int wid  = tid >> 5;
    const int lane = tid & 31;
    const int warp_m = (wid >> 1) * 32;
    const int warp_n = (wid & 1) * 64;

    const int z  = blockIdx.z;
    const int bz = z >> 3, sp = z & 7;
    Ah += (long)bz * sAb + (long)sp * sAs;
    Al += (long)bz * sAb + (long)sp * sAs;
    Bh += (long)bz * sBb + (long)sp * sBs;
    Bl += (long)bz * sBb + (long)sp * sBs;
    Cf += (long)bz * sCb + (long)sp * sCs;

    const int m0 = blockIdx.y * 128;
    const int n0 = blockIdx.x * 128;

    float acc[2][8][4] = {};
    uint4 ga[2], gb[2];

    auto ldglob = [&](int it) {
        const int pass = it >> 3;
        const int kk = (it & 7) * 32;             // K-row offset within split
        const __nv_bfloat16* Ap = (pass == 2) ? Al : Ah;
        const __nv_bfloat16* Bq = (pass == 1) ? Bl : Bh;
        #pragma unroll
        for (int i = 0; i < 2; i++) {
            const int s = tid * 2 + i;
            const int row = s >> 4, c16 = s & 15;   // 32 rows x 16 col-chunks
            ga[i] = *(const uint4*)&Ap[(long)(kk + row) * lda + m0 + c16 * 8];
            gb[i] = *(const uint4*)&Bq[(long)(kk + row) * ldb + n0 + c16 * 8];
        }
    };
    auto stsmem = [&](int buf) {
        #pragma unroll
        for (int i = 0; i < 2; i++) {
            const int s = tid * 2 + i;
            const int row = s >> 4, c16 = s & 15;
            *(uint4*)((char*)sA + buf * 8704 + row * 272 + c16 * 16) = ga[i];
            *(uint4*)((char*)sB + buf * 8704 + row * 272 + c16 * 16) = gb[i];
        }
    };

    const uint32_t baseA0 = smem_u32(sA);
    const uint32_t baseB0 = smem_u32(sB);
    // trans A: smem row = k, col = m.  Fragment tiles (match non-trans order):
    //   lanes0-7:(k0-7,m+0) 8-15:(k0-7,m+8) 16-23:(k8-15,m+0) 24-31:(k8-15,m+8)
    const uint32_t aoffl = ((lane & 7) + ((lane >> 4) & 1) * 8) * 272
                         + (warp_m + ((lane >> 3) & 1) * 8) * 2;
    // trans B: lanes0-7:(k0-7,n+0) 8-15:(k8-15,n+0) 16-23:(k0-7,n+8) 24-31:(k8-15,n+8)
    const uint32_t boffl = ((lane & 7) + ((lane >> 3) & 1) * 8) * 272
                         + (warp_n + ((lane >> 4) & 1) * 8) * 2;

    auto compute = [&](int buf) {
        const uint32_t bA = baseA0 + buf * 8704;
        const uint32_t bB = baseB0 + buf * 8704;
        #pragma unroll
        for (int k16 = 0; k16 < 2; k16++) {
            uint32_t a[2][4];
            #pragma unroll
            for (int mt = 0; mt < 2; mt++)
                ldsm_x4_t(a[mt][0], a[mt][1], a[mt][2], a[mt][3],
                          bA + aoffl + k16 * 16 * 272 + mt * 16 * 2);
            uint32_t b[4][4];
            #pragma unroll
            for (int nt2 = 0; nt2 < 4; nt2++)
                ldsm_x4_t(b[nt2][0], b[nt2][1], b[nt2][2], b[nt2][3],
                          bB + boffl + k16 * 16 * 272 + nt2 * 16 * 2);
            #pragma unroll
            for (int mt = 0; mt < 2; mt++)
                #pragma unroll
                for (int nt = 0; nt < 8; nt++)
                    mma16816(acc[mt][nt], a[mt], &b[nt >> 1][(nt & 1) * 2]);
        }
    };

    const int NCH = 24;
    ldglob(0); stsmem(0);
    __syncthreads();
    int buf = 0;
    #pragma unroll 1
    for (int it = 0; it < NCH; it++) {
        if (it + 1 < NCH) ldglob(it + 1);
        compute(buf);
        if (it + 1 < NCH) { stsmem(buf ^ 1); __syncthreads(); }
        buf ^= 1;
    }

    #pragma unroll
    for (int mt = 0; mt < 2; mt++)
        #pragma unroll
        for (int hf = 0; hf < 2; hf++) {
            const int m = m0 + warp_m + mt * 16 + (lane >> 2) + hf * 8;
            #pragma unroll
            for (int nt = 0; nt < 8; nt++) {
                const int n = n0 + warp_n + nt * 8 + (lane & 3) * 2;
                *(float2*)&Cf[(long)m * ldc + n] =
                    make_float2(acc[mt][nt][hf * 2], acc[mt][nt][hf * 2 + 1]);
            }
        }
}

// ===========================================================================
// Elementwise kernels
// ===========================================================================
__global__ void clear_kernel() {
    if (threadIdx.x < BATCH)
        ((unsigned*)(g_f + F_KMAX))[threadIdx.x] = 0u;
}

__global__ __launch_bounds__(256)
void conv_hl(const float* __restrict__ in, __nv_bfloat16* __restrict__ h,
             __nv_bfloat16* __restrict__ l, long n) {
    long i = (long)blockIdx.x * 256 + threadIdx.x;
    if (i < n) {
        float x = in[i];
        __nv_bfloat16 hi = __float2bfloat16(x);
        h[i] = hi;
        l[i] = __float2bfloat16(x - __bfloat162float(hi));
    }
}

__global__ __launch_bounds__(256)
void tconv(const float* __restrict__ in, __nv_bfloat16* __restrict__ oh,
           __nv_bfloat16* __restrict__ ol, int R, int C) {
    __shared__ float t[32][33];
    const int r0 = blockIdx.x * 32, c0 = blockIdx.y * 32;
    const int tx = threadIdx.x, ty = threadIdx.y;
    #pragma unroll
    for (int d = 0; d < 4; d++)
        t[ty + 8 * d][tx] = in[(long)(r0 + ty + 8 * d) * C + c0 + tx];
    __syncthreads();
    #pragma unroll
    for (int d = 0; d < 4; d++) {
        const int cc = c0 + ty + 8 * d;
        float x = t[tx][ty + 8 * d];
        __nv_bfloat16 hi = __float2bfloat16(x);
        long o = (long)cc * R + r0 + tx;
        oh[o] = hi;
        ol[o] = __float2bfloat16(x - __bfloat162float(hi));
    }
}

// kvs reduce (8 split-K partials) + transpose + convert -> kvsT hi/lo
__global__ __launch_bounds__(256)
void kvsred() {
    __shared__ float t[32][33];
    const int b = blockIdx.z;
    const int m0 = blockIdx.x * 32, d0 = blockIdx.y * 32;
    const int tx = threadIdx.x, ty = threadIdx.y;
    const float* p = g_f + F_PART + (long)b * 8 * SZW;
    #pragma unroll
    for (int dd = 0; dd < 4; dd++) {
        const int m = m0 + ty + 8 * dd;
        float s = 0.f;
        #pragma unroll
        for (int spl = 0; spl < 8; spl++)
            s += p[(long)spl * SZW + (long)m * 256 + d0 + tx];
        t[ty + 8 * dd][tx] = s;
    }
    __syncthreads();
    #pragma unroll
    for (int dd = 0; dd < 4; dd++) {
        const int d = d0 + ty + 8 * dd;
        float x = t[tx][ty + 8 * dd];
        __nv_bfloat16 hi = __float2bfloat16(x);
        long o = (long)b * SZW + (long)d * 256 + m0 + tx;
        g_b[B_KVSTH + o] = hi;
        g_b[B_KVSTL + o] = __float2bfloat16(x - __bfloat162float(hi));
    }
}

// kp: x from KS hi/lo, per-batch mx -> kp bf16 hi/lo
__global__ __launch_bounds__(256) void kp_kernel() {
    const int row = blockIdx.x;
    const int b   = row >> 11;
    const int t   = threadIdx.x;
    const long base = (long)row * MFEAT;
    const float x = __bfloat162float(g_b[B_KSH + base + t])
                  + __bfloat162float(g_b[B_KSL + base + t]);
    const float xp = g_f[F_XK + base + t];
    __shared__ float sm8[8];
    const float diag = 0.5f * blockSum256(x * x, sm8);
    const float mx = ord_dec(((const unsigned*)(g_f + F_KMAX))[b]);
    const float kp = 0.0625f * (expf(xp - diag - mx) + 1e-6f);
    __nv_bfloat16 hi = __float2bfloat16(kp);
    g_b[B_KPH + base + t] = hi;
    g_b[B_KPL + base + t] = __float2bfloat16(kp - __bfloat162float(hi));
}

__global__ __launch_bounds__(256) void ksump_kernel() {
    const int b = blockIdx.y, chunk = blockIdx.x, m = threadIdx.x;
    const long base = B_KPH + (long)b * L_SEQ * MFEAT;
    const long basel = B_KPL + (long)b * L_SEQ * MFEAT;
    float s = 0.f;
    const int r0 = chunk * 256;
    for (int r = 0; r < 256; r++) {
        const long o = (long)(r0 + r) * MFEAT + m;
        s += __bfloat162float(g_b[base + o]) + __bfloat162float(g_b[basel + o]);
    }
    g_f[F_KSUMP + ((long)b * 8 + chunk) * MFEAT + m] = s;
}

// qp (bf16 hi/lo) + den fused
__global__ __launch_bounds__(256) void qpden_kernel() {
    const int row = blockIdx.x;
    const int b   = row >> 11;
    const int t   = threadIdx.x;
    const long base = (long)row * MFEAT;
    const float x = __bfloat162float(g_b[B_QSH + base + t])
                  + __bfloat162float(g_b[B_QSL + base + t]);
    const float xp = g_f[F_XQ + base + t];
    __shared__ float sm8[8];
    const float diag = 0.5f * blockSum256(x * x, sm8);
    const float mx   = blockMax256(xp, sm8);
    const float qp = 0.0625f * (expf(xp - diag - mx) + 1e-6f);
    __nv_bfloat16 hi = __float2bfloat16(qp);
    g_b[B_QPH + base + t] = hi;
    g_b[B_QPL + base + t] = __float2bfloat16(qp - __bfloat162float(hi));
    float ks = 0.f;
    #pragma unroll
    for (int c = 0; c < 8; c++)
        ks += g_f[F_KSUMP + ((long)b * 8 + c) * MFEAT + t];
    const float den = blockSum256(qp * ks, sm8);
    if (t == 0) g_f[F_DEN + row] = den;
}

// ===========================================================================
// launch
// ===========================================================================
extern "C" void kernel_launch(void* const* d_in, const int* in_sizes, int n_in,
                              void* d_out, int out_size)
{
    const float* query = (const float*)d_in[0];
    const float* key   = (const float*)d_in[1];
    const float* value = (const float*)d_in[2];
    const float* Wq = (const float*)d_in[4];
    const float* bq = (const float*)d_in[5];
    const float* Wk = (const float*)d_in[6];
    const float* bk = (const float*)d_in[7];
    const float* Wv = (const float*)d_in[8];
    const float* bv = (const float*)d_in[9];
    const float* Wo = (const float*)d_in[10];
    const float* bo = (const float*)d_in[11];
    const float* proj = (const float*)d_in[12];
    const float* pos  = (const float*)d_in[13];
    float* out = (float*)d_out;

    void* fp = nullptr; cudaGetSymbolAddress(&fp, g_f);
    void* bp = nullptr; cudaGetSymbolAddress(&bp, g_b);
    float* F = (float*)fp;
    __nv_bfloat16* Bp = (__nv_bfloat16*)bp;

    clear_kernel<<<1, 32>>>();

    // weight conversions (small)
    dim3 tb(32, 8);
    tconv<<<dim3(8, 8), tb>>>(Wq, Bp + B_WQTH, Bp + B_WQTL, 256, 256);
    tconv<<<dim3(8, 8), tb>>>(Wk, Bp + B_WKTH, Bp + B_WKTL, 256, 256);
    tconv<<<dim3(8, 8), tb>>>(Wv, Bp + B_WVTH, Bp + B_WVTL, 256, 256);
    tconv<<<dim3(8, 8), tb>>>(Wo, Bp + B_WOTH, Bp + B_WOTL, 256, 256);
    conv_hl<<<256, 256>>>(proj, Bp + B_PRJH, Bp + B_PRJL, SZW);

    // projections from f32 inputs (fused hi/lo conversion), bf16-only output
    dim3 gP(2, 64, 1);
    mma_gemm<2, true, false, true, false><<<gP, 256>>>(query, nullptr, nullptr,
        Bp + B_WQTH, Bp + B_WQTL, nullptr, Bp + B_QSH, Bp + B_QSL,
        bq, nullptr, pos, 256, 256, 256, 0, 0, 0, 0);
    mma_gemm<2, true, false, true, false><<<gP, 256>>>(key, nullptr, nullptr,
        Bp + B_WKTH, Bp + B_WKTL, nullptr, Bp + B_KSH, Bp + B_KSL,
        bk, nullptr, pos, 256, 256, 256, 0, 0, 0, 0);
    mma_gemm<1, true, false, true, false><<<gP, 256>>>(value, nullptr, nullptr,
        Bp + B_WVTH, Bp + B_WVTL, nullptr, Bp + B_VH, Bp + B_VL,
        bv, nullptr, nullptr, 256, 256, 256, 0, 0, 0, 0);

    // xp = Qs @ proj^T (f32 out); xk also computes per-batch max
    mma_gemm<0, false, true, false, false><<<gP, 256>>>(nullptr, Bp + B_QSH, Bp + B_QSL,
        Bp + B_PRJH, Bp + B_PRJL, F + F_XQ, nullptr, nullptr,
        nullptr, nullptr, nullptr, 256, 256, 256, 0, 0, 0, 0);
    mma_gemm<0, false, true, false, true><<<gP, 256>>>(nullptr, Bp + B_KSH, Bp + B_KSL,
        Bp + B_PRJH, Bp + B_PRJL, F + F_XK, nullptr, nullptr,
        nullptr, nullptr, nullptr, 256, 256, 256, 0, 0, 0, 0);

    kp_kernel<<<NROWS, 256>>>();
    ksump_kernel<<<dim3(8, BATCH), 256>>>();
    qpden_kernel<<<NROWS, 256>>>();

    // kvs[b] = kp[b]^T @ v[b]  via TN GEMM (ldmatrix.trans), split-K 8
    dim3 gKVS(2, 2, 32);
    mma_gemm_tn<<<gKVS, 256>>>(Bp + B_KPH, Bp + B_KPL, Bp + B_VH, Bp + B_VL,
        F + F_PART, 256, 256, 256,
        (long)L_SEQ * MFEAT, (long)256 * MFEAT,
        (long)L_SEQ * 256,  (long)256 * 256,
        (long)8 * SZW, SZW);
    kvsred<<<dim3(8, 8, BATCH), tb>>>();

    // ctx = (qp @ kvs) / den
    dim3 gNUM(2, 16, BATCH);
    mma_gemm<3, false, false, true, false><<<gNUM, 256>>>(nullptr, Bp + B_QPH, Bp + B_QPL,
        Bp + B_KVSTH, Bp + B_KVSTL, nullptr, Bp + B_CTXH, Bp + B_CTXL,
        nullptr, F + F_DEN, nullptr, 256, 256, 256,
        (long)L_SEQ * 256, SZW, (long)L_SEQ * 256, L_SEQ);

    // out = ctx @ Wo + bo
    mma_gemm<1, false, true, false, false><<<gP, 256>>>(nullptr, Bp + B_CTXH, Bp + B_CTXL,
        Bp + B_WOTH, Bp + B_WOTL, out, nullptr, nullptr,
        bo, nullptr, nullptr, 256, 256, 256, 0, 0, 0, 0);
}

// round 6
// speedup vs baseline: 1.9027x; 1.1139x over previous
#include <cuda_runtime.h>
#include <cuda_bf16.h>
#include <math.h>
#include <stdint.h>

#define L_SEQ   2048
#define DMODEL  256
#define BATCH   4
#define MFEAT   256
#define NROWS   8192

// ===========================================================================
// Scratch
// ===========================================================================
static constexpr long SZB = (long)NROWS * DMODEL;   // 2,097,152
static constexpr long SZW = 65536;

// f32 scratch
static constexpr long F_XQ    = 0;
static constexpr long F_XK    = F_XQ + SZB;
static constexpr long F_PART  = F_XK + SZB;                 // 32 * 65536
static constexpr long F_DEN   = F_PART + SZB;
static constexpr long F_KSUMP = F_DEN + NROWS;
static constexpr long F_KMAX  = F_KSUMP + (long)BATCH * 8 * MFEAT;
static constexpr long F_TOTAL = F_KMAX + 16;
__device__ float g_f[F_TOTAL];

// bf16 scratch (hi/lo pairs adjacent: base + z*2*stride, lo = +stride)
static constexpr long B_QINH = 0;
static constexpr long B_QINL = B_QINH + SZB;
static constexpr long B_KINH = B_QINL + SZB;
static constexpr long B_KINL = B_KINH + SZB;
static constexpr long B_VINH = B_KINL + SZB;
static constexpr long B_VINL = B_VINH + SZB;
static constexpr long B_QSH  = B_VINL + SZB;
static constexpr long B_QSL  = B_QSH + SZB;
static constexpr long B_KSH  = B_QSL + SZB;
static constexpr long B_KSL  = B_KSH + SZB;
static constexpr long B_VH   = B_KSL + SZB;
static constexpr long B_VL   = B_VH  + SZB;
static constexpr long B_QPH  = B_VL  + SZB;
static constexpr long B_QPL  = B_QPH + SZB;
static constexpr long B_KPH  = B_QPL + SZB;
static constexpr long B_KPL  = B_KPH + SZB;
static constexpr long B_CTXH = B_KPL + SZB;
static constexpr long B_CTXL = B_CTXH + SZB;
static constexpr long B_KVSTH = B_CTXL + SZB;               // 4*256*256
static constexpr long B_KVSTL = B_KVSTH + 4 * SZW;
static constexpr long B_WQTH = B_KVSTL + 4 * SZW;
static constexpr long B_WQTL = B_WQTH + SZW;
static constexpr long B_WKTH = B_WQTL + SZW;
static constexpr long B_WKTL = B_WKTH + SZW;
static constexpr long B_WVTH = B_WKTL + SZW;
static constexpr long B_WVTL = B_WVTH + SZW;
static constexpr long B_WOTH = B_WVTL + SZW;
static constexpr long B_WOTL = B_WOTH + SZW;
static constexpr long B_PRJH = B_WOTL + SZW;
static constexpr long B_PRJL = B_PRJH + SZW;
static constexpr long B_TOTAL = B_PRJL + SZW;
__device__ __nv_bfloat16 g_b[B_TOTAL];

// ===========================================================================
// Helpers
// ===========================================================================
__device__ __forceinline__ uint32_t smem_u32(const void* p) {
    uint32_t a;
    asm("{ .reg .u64 t; cvta.to.shared.u64 t, %1; cvt.u32.u64 %0, t; }"
        : "=r"(a) : "l"(p));
    return a;
}
__device__ __forceinline__ void cp16(uint32_t dst, const void* src) {
    asm volatile("cp.async.cg.shared.global [%0], [%1], 16;"
                 :: "r"(dst), "l"(src) : "memory");
}
#define CP_COMMIT()  asm volatile("cp.async.commit_group;" ::: "memory")
#define CP_WAIT2()   asm volatile("cp.async.wait_group 2;" ::: "memory")
#define CP_WAITALL() asm volatile("cp.async.wait_all;" ::: "memory")

__device__ __forceinline__ void ldsm_x4(uint32_t& r0, uint32_t& r1,
                                        uint32_t& r2, uint32_t& r3, uint32_t addr) {
    asm volatile("ldmatrix.sync.aligned.m8n8.x4.shared.b16 {%0,%1,%2,%3}, [%4];"
                 : "=r"(r0), "=r"(r1), "=r"(r2), "=r"(r3) : "r"(addr));
}
__device__ __forceinline__ void ldsm_x4_t(uint32_t& r0, uint32_t& r1,
                                          uint32_t& r2, uint32_t& r3, uint32_t addr) {
    asm volatile("ldmatrix.sync.aligned.m8n8.x4.trans.shared.b16 {%0,%1,%2,%3}, [%4];"
                 : "=r"(r0), "=r"(r1), "=r"(r2), "=r"(r3) : "r"(addr));
}
__device__ __forceinline__ void mma16816(float* d, const uint32_t* a, const uint32_t* b) {
    asm volatile("mma.sync.aligned.m16n8k16.row.col.f32.bf16.bf16.f32 "
                 "{%0,%1,%2,%3}, {%4,%5,%6,%7}, {%8,%9}, {%0,%1,%2,%3};"
                 : "+f"(d[0]), "+f"(d[1]), "+f"(d[2]), "+f"(d[3])
                 : "r"(a[0]), "r"(a[1]), "r"(a[2]), "r"(a[3]), "r"(b[0]), "r"(b[1]));
}
__device__ __forceinline__ unsigned ord_enc(float f) {
    unsigned u = __float_as_uint(f);
    return (u & 0x80000000u) ? ~u : (u | 0x80000000u);
}
__device__ __forceinline__ float ord_dec(unsigned u) {
    return __uint_as_float((u & 0x80000000u) ? (u & 0x7fffffffu) : ~u);
}
__device__ __forceinline__ float blockSum256(float v, float* sm8) {
    #pragma unroll
    for (int o = 16; o; o >>= 1) v += __shfl_xor_sync(0xffffffffu, v, o);
    if ((threadIdx.x & 31) == 0) sm8[threadIdx.x >> 5] = v;
    __syncthreads();
    float s = 0.f;
    #pragma unroll
    for (int i = 0; i < 8; i++) s += sm8[i];
    __syncthreads();
    return s;
}
__device__ __forceinline__ float blockMax256(float v, float* sm8) {
    #pragma unroll
    for (int o = 16; o; o >>= 1) v = fmaxf(v, __shfl_xor_sync(0xffffffffu, v, o));
    if ((threadIdx.x & 31) == 0) sm8[threadIdx.x >> 5] = v;
    __syncthreads();
    float s = sm8[0];
    #pragma unroll
    for (int i = 1; i < 8; i++) s = fmaxf(s, sm8[i]);
    __syncthreads();
    return s;
}

// ===========================================================================
// NT GEMM, 4-stage cp.async pipeline.
//   C = (Ah+Al) @ (Bh+Bl)^T-as-[N,K], 3-pass bf16 split, fp32 acc, K=256.
//   Tile 128x128, 8 warps (4Mx2N), K-chunk 16, 48 chunks.
//   epiMode: 0 none, 1 +bias[n], 2 +bias+rotary+0.25, 3 /den[m],
//            4 = per-z: z<2 -> 2, z==2 -> 1 (merged qkv projections)
//   domaxZ: if blockIdx.z == domaxZ, atomicMax raw acc into g_f[F_KMAX + m0>>11]
// ===========================================================================
__global__ __launch_bounds__(256)
void mma_nt(const __nv_bfloat16* __restrict__ Ah, const __nv_bfloat16* __restrict__ Al,
            const __nv_bfloat16* __restrict__ Bh, const __nv_bfloat16* __restrict__ Bl,
            float* __restrict__ Cf, __nv_bfloat16* __restrict__ Ch,
            __nv_bfloat16* __restrict__ Cl,
            const float* __restrict__ bias0, const float* __restrict__ bias1,
            const float* __restrict__ bias2,
            const float* __restrict__ den, const float* __restrict__ pos,
            int lda, int ldb, int ldc,
            long sAb, long sBb, long sCb, long sDen,
            int epiMode, int domaxZ)
{
    // 4 stages x (A: 128 rows x 48B) x 2 operands = 49152 B exactly
    __shared__ __align__(16) char smemBuf[49152];

    const int tid  = threadIdx.x;
    const int wid  = tid >> 5;
    const int lane = tid & 31;
    const int warp_m = (wid >> 1) * 32;
    const int warp_n = (wid & 1) * 64;

    const int z = blockIdx.z;
    const int epi = (epiMode == 4) ? ((z < 2) ? 2 : 1) : epiMode;
    const float* bias = (z == 0) ? bias0 : (z == 1) ? bias1 : bias2;
    Ah += (long)z * sAb; Al += (long)z * sAb;
    Bh += (long)z * sBb; Bl += (long)z * sBb;
    if (Cf) Cf += (long)z * sCb;
    if (Ch) { Ch += (long)z * sCb; Cl += (long)z * sCb; }
    if (epi == 3) den += (long)z * sDen;

    const int m0 = blockIdx.y * 128;
    const int n0 = blockIdx.x * 128;
    const uint32_t sbase = smem_u32(smemBuf);

    // per-thread load slot: row = tid>>1 (0..127), c16 = tid&1
    const int lrow = tid >> 1;
    const int lc16 = tid & 1;

    auto ldchunk = [&](int ck, int slot) {
        const int pass = ck >> 4;
        const int kk = (ck & 15) * 16;
        const __nv_bfloat16* Ap = (pass == 2) ? Al : Ah;
        const __nv_bfloat16* Bq = (pass == 1) ? Bl : Bh;
        const uint32_t dA = sbase + slot * 12288 + lrow * 48 + lc16 * 16;
        cp16(dA,        Ap + (long)(m0 + lrow) * lda + kk + lc16 * 8);
        cp16(dA + 6144, Bq + (long)(n0 + lrow) * ldb + kk + lc16 * 8);
    };

    const uint32_t aoffl = (warp_m + (lane & 15)) * 48 + (lane >> 4) * 16;
    const uint32_t boffl = (warp_n + (lane & 7) + ((lane >> 4) & 1) * 8) * 48
                         + ((lane >> 3) & 1) * 16;

    float acc[2][8][4] = {};

    auto compute = [&](int slot) {
        const uint32_t bA = sbase + slot * 12288;
        const uint32_t bB = bA + 6144;
        uint32_t a[2][4];
        #pragma unroll
        for (int mt = 0; mt < 2; mt++)
            ldsm_x4(a[mt][0], a[mt][1], a[mt][2], a[mt][3],
                    bA + aoffl + mt * 16 * 48);
        uint32_t b[4][4];
        #pragma unroll
        for (int nt2 = 0; nt2 < 4; nt2++)
            ldsm_x4(b[nt2][0], b[nt2][1], b[nt2][2], b[nt2][3],
                    bB + boffl + nt2 * 16 * 48);
        #pragma unroll
        for (int mt = 0; mt < 2; mt++)
            #pragma unroll
            for (int nt = 0; nt < 8; nt++)
                mma16816(acc[mt][nt], a[mt], &b[nt >> 1][(nt & 1) * 2]);
    };

    // prologue: 3 chunks in flight
    ldchunk(0, 0); CP_COMMIT();
    ldchunk(1, 1); CP_COMMIT();
    ldchunk(2, 2); CP_COMMIT();

    #pragma unroll 1
    for (int it = 0; it < 48; it++) {
        CP_WAIT2();
        __syncthreads();
        const int pf = it + 3;
        if (pf < 48) ldchunk(pf, pf & 3);
        CP_COMMIT();
        compute(it & 3);
    }
    CP_WAITALL();

    if (z == domaxZ) {
        float mx = -3.402823466e38f;
        #pragma unroll
        for (int mt = 0; mt < 2; mt++)
            #pragma unroll
            for (int nt = 0; nt < 8; nt++)
                #pragma unroll
                for (int q = 0; q < 4; q++)
                    mx = fmaxf(mx, acc[mt][nt][q]);
        __syncthreads();
        mx = blockMax256(mx, (float*)smemBuf);
        if (tid == 0)
            atomicMax((unsigned*)(g_f + F_KMAX) + (m0 >> 11), ord_enc(mx));
    }

    // epilogue
    #pragma unroll
    for (int mt = 0; mt < 2; mt++) {
        #pragma unroll
        for (int hf = 0; hf < 2; hf++) {
            const int m = m0 + warp_m + mt * 16 + (lane >> 2) + hf * 8;
            float invd = 1.0f;
            if (epi == 3) invd = 1.0f / den[m];
            const int l = m & (L_SEQ - 1);
            #pragma unroll
            for (int nt = 0; nt < 8; nt++) {
                const int n = n0 + warp_n + nt * 8 + (lane & 3) * 2;
                float v0 = acc[mt][nt][hf * 2 + 0];
                float v1 = acc[mt][nt][hf * 2 + 1];
                if (epi == 1 || epi == 2) { v0 += bias[n]; v1 += bias[n + 1]; }
                if (epi == 2) {
                    const float sn = pos[(long)l * DMODEL + n];
                    const float cs = pos[(long)l * DMODEL + n + 1];
                    const float q0 = v0 * cs - v1 * sn;
                    const float q1 = v1 * cs + v0 * sn;
                    v0 = q0 * 0.25f; v1 = q1 * 0.25f;
                }
                if (epi == 3) { v0 *= invd; v1 *= invd; }
                if (Cf)
                    *(float2*)&Cf[(long)m * ldc + n] = make_float2(v0, v1);
                if (Ch) {
                    __nv_bfloat16 h0 = __float2bfloat16(v0);
                    __nv_bfloat16 h1 = __float2bfloat16(v1);
                    float l0 = v0 - __bfloat162float(h0);
                    float l1 = v1 - __bfloat162float(h1);
                    unsigned hp = ((unsigned)__bfloat16_as_ushort(h1) << 16)
                                | __bfloat16_as_ushort(h0);
                    unsigned lp = ((unsigned)__bfloat16_as_ushort(__float2bfloat16(l1)) << 16)
                                | __bfloat16_as_ushort(__float2bfloat16(l0));
                    *(unsigned*)&Ch[(long)m * ldc + n] = hp;
                    *(unsigned*)&Cl[(long)m * ldc + n] = lp;
                }
            }
        }
    }
}

// ===========================================================================
// TN GEMM, 4-stage cp.async pipeline (kvs): C[M,N] = (Ah+Al)^T @ (Bh+Bl)
//   A [K,M] (kp: [L,256]); B [K,N] (v: [L,256]); ldmatrix .trans.
//   Split-K: z = bz*8+sp, 256 K-rows/split; K-chunk 16, 48 chunks; f32 out.
// ===========================================================================
__global__ __launch_bounds__(256)
void mma_tn(const __nv_bfloat16* __restrict__ Ah, const __nv_bfloat16* __restrict__ Al,
            const __nv_bfloat16* __restrict__ Bh, const __nv_bfloat16* __restrict__ Bl,
            float* __restrict__ Cf,
            int lda, int ldb, int ldc,
            long sAb, long sAs, long sBb, long sBs, long sCb, long sCs)
{
    // 4 stages x (16 rows x 272B) x 2 = 34816 B
    __shared__ __align__(16) char smemBuf[34816];

    const int tid  = threadIdx.x;
    const int wid  = tid >> 5;
    const int lane = tid & 31;
    const int warp_m = (wid >> 1) * 32;
    const int warp_n = (wid & 1) * 64;

    const int z  = blockIdx.z;
    const int bz = z >> 3, sp = z & 7;
    Ah += (long)bz * sAb + (long)sp * sAs;
    Al += (long)bz * sAb + (long)sp * sAs;
    Bh += (long)bz * sBb + (long)sp * sBs;
    Bl += (long)bz * sBb + (long)sp * sBs;
    Cf += (long)bz * sCb + (long)sp * sCs;

    const int m0 = blockIdx.y * 128;
    const int n0 = blockIdx.x * 128;
    const uint32_t sbase = smem_u32(smemBuf);

    const int lrow = tid >> 4;   // 0..15
    const int lc16 = tid & 15;   // 0..15

    auto ldchunk = [&](int ck, int slot) {
        const int pass = ck >> 4;
        const int kk = (ck & 15) * 16;
        const __nv_bfloat16* Ap = (pass == 2) ? Al : Ah;
        const __nv_bfloat16* Bq = (pass == 1) ? Bl : Bh;
        const uint32_t dA = sbase + slot * 8704 + lrow * 272 + lc16 * 16;
        cp16(dA,        Ap + (long)(kk + lrow) * lda + m0 + lc16 * 8);
        cp16(dA + 4352, Bq + (long)(kk + lrow) * ldb + n0 + lc16 * 8);
    };

    const uint32_t aoffl = ((lane & 7) + ((lane >> 4) & 1) * 8) * 272
                         + (warp_m + ((lane >> 3) & 1) * 8) * 2;
    const uint32_t boffl = ((lane & 7) + ((lane >> 3) & 1) * 8) * 272
                         + (warp_n + ((lane >> 4) & 1) * 8) * 2;

    float acc[2][8][4] = {};

    auto compute = [&](int slot) {
        const uint32_t bA = sbase + slot * 8704;
        const uint32_t bB = bA + 4352;
        uint32_t a[2][4];
        #pragma unroll
        for (int mt = 0; mt < 2; mt++)
            ldsm_x4_t(a[mt][0], a[mt][1], a[mt][2], a[mt][3],
                      bA + aoffl + mt * 16 * 2);
        uint32_t b[4][4];
        #pragma unroll
        for (int nt2 = 0; nt2 < 4; nt2++)
            ldsm_x4_t(b[nt2][0], b[nt2][1], b[nt2][2], b[nt2][3],
                      bB + boffl + nt2 * 16 * 2);
        #pragma unroll
        for (int mt = 0; mt < 2; mt++)
            #pragma unroll
            for (int nt = 0; nt < 8; nt++)
                mma16816(acc[mt][nt], a[mt], &b[nt >> 1][(nt & 1) * 2]);
    };

    ldchunk(0, 0); CP_COMMIT();
    ldchunk(1, 1); CP_COMMIT();
    ldchunk(2, 2); CP_COMMIT();

    #pragma unroll 1
    for (int it = 0; it < 48; it++) {
        CP_WAIT2();
        __syncthreads();
        const int pf = it + 3;
        if (pf < 48) ldchunk(pf, pf & 3);
        CP_COMMIT();
        compute(it & 3);
    }
    CP_WAITALL();

    #pragma unroll
    for (int mt = 0; mt < 2; mt++)
        #pragma unroll
        for (int hf = 0; hf < 2; hf++) {
            const int m = m0 + warp_m + mt * 16 + (lane >> 2) + hf * 8;
            #pragma unroll
            for (int nt = 0; nt < 8; nt++) {
                const int n = n0 + warp_n + nt * 8 + (lane & 3) * 2;
                *(float2*)&Cf[(long)m * ldc + n] =
                    make_float2(acc[mt][nt][hf * 2], acc[mt][nt][hf * 2 + 1]);
            }
        }
}

// ===========================================================================
// Elementwise kernels
// ===========================================================================
__global__ void clear_kernel() {
    if (threadIdx.x < BATCH)
        ((unsigned*)(g_f + F_KMAX))[threadIdx.x] = 0u;
}

// vectorized f32 -> bf16 hi/lo; z selects input; out = base + z*2*stride (+stride)
__global__ __launch_bounds__(256)
void conv4(const float* __restrict__ in0, const float* __restrict__ in1,
           const float* __restrict__ in2, __nv_bfloat16* __restrict__ outBase,
           long stride, long n4) {
    const float* in = (blockIdx.z == 0) ? in0 : (blockIdx.z == 1) ? in1 : in2;
    __nv_bfloat16* h = outBase + (long)blockIdx.z * 2 * stride;
    __nv_bfloat16* l = h + stride;
    long i = (long)blockIdx.x * 256 + threadIdx.x;
    if (i < n4) {
        float4 x = ((const float4*)in)[i];
        float xs[4] = {x.x, x.y, x.z, x.w};
        unsigned short hh[4], ll[4];
        #pragma unroll
        for (int j = 0; j < 4; j++) {
            __nv_bfloat16 hi = __float2bfloat16(xs[j]);
            hh[j] = __bfloat16_as_ushort(hi);
            ll[j] = __bfloat16_as_ushort(__float2bfloat16(xs[j] - __bfloat162float(hi)));
        }
        ((uint2*)h)[i] = make_uint2((unsigned)hh[0] | ((unsigned)hh[1] << 16),
                                    (unsigned)hh[2] | ((unsigned)hh[3] << 16));
        ((uint2*)l)[i] = make_uint2((unsigned)ll[0] | ((unsigned)ll[1] << 16),
                                    (unsigned)ll[2] | ((unsigned)ll[3] << 16));
    }
}

// weight transpose + hi/lo convert, merged over z = {Wq,Wk,Wv,Wo}
__global__ __launch_bounds__(256)
void tconvW(const float* __restrict__ w0, const float* __restrict__ w1,
            const float* __restrict__ w2, const float* __restrict__ w3,
            __nv_bfloat16* __restrict__ outBase) {
    __shared__ float t[32][33];
    const int zz = blockIdx.z;
    const float* in = (zz == 0) ? w0 : (zz == 1) ? w1 : (zz == 2) ? w2 : w3;
    __nv_bfloat16* oh = outBase + (long)zz * 2 * SZW;
    __nv_bfloat16* ol = oh + SZW;
    const int r0 = blockIdx.x * 32, c0 = blockIdx.y * 32;
    const int tx = threadIdx.x, ty = threadIdx.y;
    #pragma unroll
    for (int d = 0; d < 4; d++)
        t[ty + 8 * d][tx] = in[(long)(r0 + ty + 8 * d) * 256 + c0 + tx];
    __syncthreads();
    #pragma unroll
    for (int d = 0; d < 4; d++) {
        const int cc = c0 + ty + 8 * d;
        float x = t[tx][ty + 8 * d];
        __nv_bfloat16 hi = __float2bfloat16(x);
        long o = (long)cc * 256 + r0 + tx;
        oh[o] = hi;
        ol[o] = __float2bfloat16(x - __bfloat162float(hi));
    }
}

// kvs reduce (8 split-K partials) + transpose + convert -> kvsT hi/lo
__global__ __launch_bounds__(256)
void kvsred() {
    __shared__ float t[32][33];
    const int b = blockIdx.z;
    const int m0 = blockIdx.x * 32, d0 = blockIdx.y * 32;
    const int tx = threadIdx.x, ty = threadIdx.y;
    const float* p = g_f + F_PART + (long)b * 8 * SZW;
    #pragma unroll
    for (int dd = 0; dd < 4; dd++) {
        const int m = m0 + ty + 8 * dd;
        float s = 0.f;
        #pragma unroll
        for (int spl = 0; spl < 8; spl++)
            s += p[(long)spl * SZW + (long)m * 256 + d0 + tx];
        t[ty + 8 * dd][tx] = s;
    }
    __syncthreads();
    #pragma unroll
    for (int dd = 0; dd < 4; dd++) {
        const int d = d0 + ty + 8 * dd;
        float x = t[tx][ty + 8 * dd];
        __nv_bfloat16 hi = __float2bfloat16(x);
        long o = (long)b * SZW + (long)d * 256 + m0 + tx;
        g_b[B_KVSTH + o] = hi;
        g_b[B_KVSTL + o] = __float2bfloat16(x - __bfloat162float(hi));
    }
}

__global__ __launch_bounds__(256) void kp_kernel() {
    const int row = blockIdx.x;
    const int b   = row >> 11;
    const int t   = threadIdx.x;
    const long base = (long)row * MFEAT;
    const float x = __bfloat162float(g_b[B_KSH + base + t])
                  + __bfloat162float(g_b[B_KSL + base + t]);
    const float xp = g_f[F_XK + base + t];
    __shared__ float sm8[8];
    const float diag = 0.5f * blockSum256(x * x, sm8);
    const float mx = ord_dec(((const unsigned*)(g_f + F_KMAX))[b]);
    const float kp = 0.0625f * (expf(xp - diag - mx) + 1e-6f);
    __nv_bfloat16 hi = __float2bfloat16(kp);
    g_b[B_KPH + base + t] = hi;
    g_b[B_KPL + base + t] = __float2bfloat16(kp - __bfloat162float(hi));
}

__global__ __launch_bounds__(256) void ksump_kernel() {
    const int b = blockIdx.y, chunk = blockIdx.x, m = threadIdx.x;
    const long baseh = B_KPH + (long)b * L_SEQ * MFEAT;
    const long basel = B_KPL + (long)b * L_SEQ * MFEAT;
    float s = 0.f;
    const int r0 = chunk * 256;
    for (int r = 0; r < 256; r++) {
        const long o = (long)(r0 + r) * MFEAT + m;
        s += __bfloat162float(g_b[baseh + o]) + __bfloat162float(g_b[basel + o]);
    }
    g_f[F_KSUMP + ((long)b * 8 + chunk) * MFEAT + m] = s;
}

__global__ __launch_bounds__(256) void qpden_kernel() {
    const int row = blockIdx.x;
    const int b   = row >> 11;
    const int t   = threadIdx.x;
    const long base = (long)row * MFEAT;
    const float x = __bfloat162float(g_b[B_QSH + base + t])
                  + __bfloat162float(g_b[B_QSL + base + t]);
    const float xp = g_f[F_XQ + base + t];
    __shared__ float sm8[8];
    const float diag = 0.5f * blockSum256(x * x, sm8);
    const float mx   = blockMax256(xp, sm8);
    const float qp = 0.0625f * (expf(xp - diag - mx) + 1e-6f);
    __nv_bfloat16 hi = __float2bfloat16(qp);
    g_b[B_QPH + base + t] = hi;
    g_b[B_QPL + base + t] = __float2bfloat16(qp - __bfloat162float(hi));
    float ks = 0.f;
    #pragma unroll
    for (int c = 0; c < 8; c++)
        ks += g_f[F_KSUMP + ((long)b * 8 + c) * MFEAT + t];
    const float den = blockSum256(qp * ks, sm8);
    if (t == 0) g_f[F_DEN + row] = den;
}

// ===========================================================================
// launch
// ===========================================================================
extern "C" void kernel_launch(void* const* d_in, const int* in_sizes, int n_in,
                              void* d_out, int out_size)
{
    const float* query = (const float*)d_in[0];
    const float* key   = (const float*)d_in[1];
    const float* value = (const float*)d_in[2];
    const float* Wq = (const float*)d_in[4];
    const float* bq = (const float*)d_in[5];
    const float* Wk = (const float*)d_in[6];
    const float* bk = (const float*)d_in[7];
    const float* Wv = (const float*)d_in[8];
    const float* bv = (const float*)d_in[9];
    const float* Wo = (const float*)d_in[10];
    const float* bo = (const float*)d_in[11];
    const float* proj = (const float*)d_in[12];
    const float* pos  = (const float*)d_in[13];
    float* out = (float*)d_out;

    void* fp = nullptr; cudaGetSymbolAddress(&fp, g_f);
    void* bp = nullptr; cudaGetSymbolAddress(&bp, g_b);
    float* F = (float*)fp;
    __nv_bfloat16* Bp = (__nv_bfloat16*)bp;

    clear_kernel<<<1, 32>>>();

    // conversions: weights (1 launch), q/k/v inputs (1 launch), proj (1 launch)
    dim3 tb(32, 8);
    tconvW<<<dim3(8, 8, 4), tb>>>(Wq, Wk, Wv, Wo, Bp + B_WQTH);
    conv4<<<dim3((unsigned)(SZB / 1024), 1, 3), 256>>>(query, key, value,
                                                       Bp + B_QINH, SZB, SZB / 4);
    conv4<<<dim3(64, 1, 1), 256>>>(proj, proj, proj, Bp + B_PRJH, SZW, SZW / 4);

    // merged q/k/v projections: z=0,1 rotary+bias, z=2 bias (epiMode=4)
    mma_nt<<<dim3(2, 64, 3), 256>>>(
        Bp + B_QINH, Bp + B_QINL + 0, Bp + B_WQTH, Bp + B_WQTL,
        nullptr, Bp + B_QSH, Bp + B_QSL,
        bq, bk, bv, nullptr, pos,
        256, 256, 256, 2 * SZB, 2 * SZW, 2 * SZB, 0, 4, -1);

    // merged xq/xk: z=0 -> XQ, z=1 -> XK (+per-batch max)
    mma_nt<<<dim3(2, 64, 2), 256>>>(
        Bp + B_QSH, Bp + B_QSL, Bp + B_PRJH, Bp + B_PRJL,
        F + F_XQ, nullptr, nullptr,
        nullptr, nullptr, nullptr, nullptr, nullptr,
        256, 256, 256, 2 * SZB, 0, SZB, 0, 0, 1);

    kp_kernel<<<NROWS, 256>>>();
    ksump_kernel<<<dim3(8, BATCH), 256>>>();
    qpden_kernel<<<NROWS, 256>>>();

    // kvs[b] = kp[b]^T @ v[b] (TN, split-K 8)
    mma_tn<<<dim3(2, 2, 32), 256>>>(Bp + B_KPH, Bp + B_KPL, Bp + B_VH, Bp + B_VL,
        F + F_PART, 256, 256, 256,
        (long)L_SEQ * MFEAT, (long)256 * MFEAT,
        (long)L_SEQ * 256,  (long)256 * 256,
        (long)8 * SZW, SZW);
    kvsred<<<dim3(8, 8, BATCH), tb>>>();

    // ctx = (qp @ kvs) / den (batched z = b)
    mma_nt<<<dim3(2, 16, BATCH), 256>>>(
        Bp + B_QPH, Bp + B_QPL, Bp + B_KVSTH, Bp + B_KVSTL,
        nullptr, Bp + B_CTXH, Bp + B_CTXL,
        nullptr, nullptr, nullptr, F + F_DEN, nullptr,
        256, 256, 256, (long)L_SEQ * 256, SZW, (long)L_SEQ * 256, L_SEQ,
        3, -1);

    // out = ctx @ Wo + bo
    mma_nt<<<dim3(2, 64, 1), 256>>>(
        Bp + B_CTXH, Bp + B_CTXL, Bp + B_WOTH, Bp + B_WOTL,
        out, nullptr, nullptr,
        bo, bo, bo, nullptr, nullptr,
        256, 256, 256, 0, 0, 0, 0, 1, -1);
}

// round 7
// speedup vs baseline: 2.1962x; 1.1543x over previous
#include <cuda_runtime.h>
#include <cuda_bf16.h>
#include <math.h>
#include <stdint.h>

#define L_SEQ   2048
#define DMODEL  256
#define BATCH   4
#define MFEAT   256
#define NROWS   8192

// ===========================================================================
// Scratch
// ===========================================================================
static constexpr long SZB = (long)NROWS * DMODEL;   // 2,097,152
static constexpr long SZW = 65536;
static constexpr int  KCH = 64;                     // ksum chunks per batch

// f32 scratch
static constexpr long F_XQ    = 0;
static constexpr long F_XK    = F_XQ + SZB;
static constexpr long F_PART  = F_XK + SZB;                 // 32 * 65536
static constexpr long F_DEN   = F_PART + SZB;
static constexpr long F_KSUMP = F_DEN + NROWS;
static constexpr long F_KMAX  = F_KSUMP + (long)BATCH * KCH * MFEAT;
static constexpr long F_TOTAL = F_KMAX + 16;
__device__ float g_f[F_TOTAL];

// bf16 scratch (hi/lo pairs adjacent: base + z*2*stride, lo = +stride)
static constexpr long B_QINH = 0;
static constexpr long B_QINL = B_QINH + SZB;
static constexpr long B_KINH = B_QINL + SZB;
static constexpr long B_KINL = B_KINH + SZB;
static constexpr long B_VINH = B_KINL + SZB;
static constexpr long B_VINL = B_VINH + SZB;
static constexpr long B_QSH  = B_VINL + SZB;
static constexpr long B_QSL  = B_QSH + SZB;
static constexpr long B_KSH  = B_QSL + SZB;
static constexpr long B_KSL  = B_KSH + SZB;
static constexpr long B_VH   = B_KSL + SZB;
static constexpr long B_VL   = B_VH  + SZB;
static constexpr long B_QPH  = B_VL  + SZB;
static constexpr long B_QPL  = B_QPH + SZB;
static constexpr long B_KPH  = B_QPL + SZB;
static constexpr long B_KPL  = B_KPH + SZB;
static constexpr long B_CTXH = B_KPL + SZB;
static constexpr long B_CTXL = B_CTXH + SZB;
static constexpr long B_KVSTH = B_CTXL + SZB;               // 4*256*256
static constexpr long B_KVSTL = B_KVSTH + 4 * SZW;
static constexpr long B_WQTH = B_KVSTL + 4 * SZW;
static constexpr long B_WQTL = B_WQTH + SZW;
static constexpr long B_WKTH = B_WQTL + SZW;
static constexpr long B_WKTL = B_WKTH + SZW;
static constexpr long B_WVTH = B_WKTL + SZW;
static constexpr long B_WVTL = B_WVTH + SZW;
static constexpr long B_WOTH = B_WVTL + SZW;
static constexpr long B_WOTL = B_WOTH + SZW;
static constexpr long B_PRJH = B_WOTL + SZW;
static constexpr long B_PRJL = B_PRJH + SZW;
static constexpr long B_TOTAL = B_PRJL + SZW;
__device__ __nv_bfloat16 g_b[B_TOTAL];

// ===========================================================================
// Helpers
// ===========================================================================
__device__ __forceinline__ uint32_t smem_u32(const void* p) {
    uint32_t a;
    asm("{ .reg .u64 t; cvta.to.shared.u64 t, %1; cvt.u32.u64 %0, t; }"
        : "=r"(a) : "l"(p));
    return a;
}
__device__ __forceinline__ void cp16(uint32_t dst, const void* src) {
    asm volatile("cp.async.cg.shared.global [%0], [%1], 16;"
                 :: "r"(dst), "l"(src) : "memory");
}
#define CP_COMMIT()  asm volatile("cp.async.commit_group;" ::: "memory")
#define CP_WAIT2()   asm volatile("cp.async.wait_group 2;" ::: "memory")
#define CP_WAITALL() asm volatile("cp.async.wait_all;" ::: "memory")

__device__ __forceinline__ void ldsm_x4(uint32_t& r0, uint32_t& r1,
                                        uint32_t& r2, uint32_t& r3, uint32_t addr) {
    asm volatile("ldmatrix.sync.aligned.m8n8.x4.shared.b16 {%0,%1,%2,%3}, [%4];"
                 : "=r"(r0), "=r"(r1), "=r"(r2), "=r"(r3) : "r"(addr));
}
__device__ __forceinline__ void ldsm_x4_t(uint32_t& r0, uint32_t& r1,
                                          uint32_t& r2, uint32_t& r3, uint32_t addr) {
    asm volatile("ldmatrix.sync.aligned.m8n8.x4.trans.shared.b16 {%0,%1,%2,%3}, [%4];"
                 : "=r"(r0), "=r"(r1), "=r"(r2), "=r"(r3) : "r"(addr));
}
__device__ __forceinline__ void mma16816(float* d, const uint32_t* a, const uint32_t* b) {
    asm volatile("mma.sync.aligned.m16n8k16.row.col.f32.bf16.bf16.f32 "
                 "{%0,%1,%2,%3}, {%4,%5,%6,%7}, {%8,%9}, {%0,%1,%2,%3};"
                 : "+f"(d[0]), "+f"(d[1]), "+f"(d[2]), "+f"(d[3])
                 : "r"(a[0]), "r"(a[1]), "r"(a[2]), "r"(a[3]), "r"(b[0]), "r"(b[1]));
}
__device__ __forceinline__ unsigned ord_enc(float f) {
    unsigned u = __float_as_uint(f);
    return (u & 0x80000000u) ? ~u : (u | 0x80000000u);
}
__device__ __forceinline__ float ord_dec(unsigned u) {
    return __uint_as_float((u & 0x80000000u) ? (u & 0x7fffffffu) : ~u);
}
__device__ __forceinline__ float blockSum256(float v, float* sm8) {
    #pragma unroll
    for (int o = 16; o; o >>= 1) v += __shfl_xor_sync(0xffffffffu, v, o);
    if ((threadIdx.x & 31) == 0) sm8[threadIdx.x >> 5] = v;
    __syncthreads();
    float s = 0.f;
    #pragma unroll
    for (int i = 0; i < 8; i++) s += sm8[i];
    __syncthreads();
    return s;
}
__device__ __forceinline__ float blockMax256(float v, float* sm8) {
    #pragma unroll
    for (int o = 16; o; o >>= 1) v = fmaxf(v, __shfl_xor_sync(0xffffffffu, v, o));
    if ((threadIdx.x & 31) == 0) sm8[threadIdx.x >> 5] = v;
    __syncthreads();
    float s = sm8[0];
    #pragma unroll
    for (int i = 1; i < 8; i++) s = fmaxf(s, sm8[i]);
    __syncthreads();
    return s;
}

// ===========================================================================
// NT GEMM, K-chunk 32, 4-stage cp.async pipeline (dynamic smem 81920B).
//   C = (Ah+Al) @ (Bh+Bl)^T-as-[N,K], 3-pass bf16 split, fp32 acc, K=256.
//   Tile 128x128, 8 warps (4Mx2N), 24 chunks. All leading dims = 256.
//   epiMode: 0 none, 1 +bias[n], 2 +bias+rotary+0.25, 3 /den[m],
//            4 per-z: z<2 -> 2, z==2 -> 1
//   domaxZ: if z == domaxZ, atomicMax raw acc into g_f[F_KMAX + m0>>11]
// ===========================================================================
__global__ __launch_bounds__(256, 2)
void mma_nt(const __nv_bfloat16* __restrict__ Ah, const __nv_bfloat16* __restrict__ Al,
            const __nv_bfloat16* __restrict__ Bh, const __nv_bfloat16* __restrict__ Bl,
            float* __restrict__ Cf, __nv_bfloat16* __restrict__ Ch,
            __nv_bfloat16* __restrict__ Cl,
            const float* __restrict__ bias0, const float* __restrict__ bias1,
            const float* __restrict__ bias2,
            const float* __restrict__ den, const float* __restrict__ pos,
            long sAb, long sBb, long sCb, long sDen,
            int epiMode, int domaxZ)
{
    extern __shared__ __align__(16) char smemBuf[];
    // stage = 128 rows x 80B x 2 operands = 20480B; 4 stages

    const int tid  = threadIdx.x;
    const int wid  = tid >> 5;
    const int lane = tid & 31;
    const int warp_m = (wid >> 1) * 32;
    const int warp_n = (wid & 1) * 64;

    const int z = blockIdx.z;
    const int epi = (epiMode == 4) ? ((z < 2) ? 2 : 1) : epiMode;
    const float* bias = (z == 0) ? bias0 : (z == 1) ? bias1 : bias2;
    if (Cf) Cf += (long)z * sCb;
    if (Ch) { Ch += (long)z * sCb; Cl += (long)z * sCb; }
    if (epi == 3) den += (long)z * sDen;

    const int m0 = blockIdx.y * 128;
    const int n0 = blockIdx.x * 128;
    const uint32_t sbase = smem_u32(smemBuf);

    // per-thread load geometry: row = tid>>1, two adjacent 16B chunks
    const int lrow = tid >> 1;
    const int lcol = (tid & 1) * 16;      // element offset within row (32B)
    const long zA = (long)z * sAb;
    const long zB = (long)z * sBb;
    const __nv_bfloat16* aH = Ah + zA + (long)(m0 + lrow) * 256 + lcol;
    const __nv_bfloat16* aL = Al + zA + (long)(m0 + lrow) * 256 + lcol;
    const __nv_bfloat16* bH = Bh + zB + (long)(n0 + lrow) * 256 + lcol;
    const __nv_bfloat16* bL = Bl + zB + (long)(n0 + lrow) * 256 + lcol;
    const uint32_t dstA = sbase + lrow * 80 + (tid & 1) * 32;
    const uint32_t dstB = dstA + 10240;

    auto ldchunk = [&](int ck, int slot) {
        const int pass = ck >> 3;
        const int kk = (ck & 7) * 32;
        const __nv_bfloat16* Ap = ((pass == 2) ? aL : aH) + kk;
        const __nv_bfloat16* Bq = ((pass == 1) ? bL : bH) + kk;
        const uint32_t so = slot * 20480;
        cp16(dstA + so,      Ap);
        cp16(dstA + so + 16, Ap + 8);
        cp16(dstB + so,      Bq);
        cp16(dstB + so + 16, Bq + 8);
    };

    const uint32_t aoffl = (warp_m + (lane & 15)) * 80 + (lane >> 4) * 16;
    const uint32_t boffl = (warp_n + (lane & 7) + ((lane >> 4) & 1) * 8) * 80
                         + ((lane >> 3) & 1) * 16;

    float acc[2][8][4] = {};

    auto compute = [&](int slot) {
        const uint32_t bA = sbase + slot * 20480;
        const uint32_t bB = bA + 10240;
        #pragma unroll
        for (int k16 = 0; k16 < 2; k16++) {
            uint32_t a[2][4];
            #pragma unroll
            for (int mt = 0; mt < 2; mt++)
                ldsm_x4(a[mt][0], a[mt][1], a[mt][2], a[mt][3],
                        bA + aoffl + mt * 16 * 80 + k16 * 32);
            uint32_t b[4][4];
            #pragma unroll
            for (int nt2 = 0; nt2 < 4; nt2++)
                ldsm_x4(b[nt2][0], b[nt2][1], b[nt2][2], b[nt2][3],
                        bB + boffl + nt2 * 16 * 80 + k16 * 32);
            #pragma unroll
            for (int mt = 0; mt < 2; mt++)
                #pragma unroll
                for (int nt = 0; nt < 8; nt++)
                    mma16816(acc[mt][nt], a[mt], &b[nt >> 1][(nt & 1) * 2]);
        }
    };

    ldchunk(0, 0); CP_COMMIT();
    ldchunk(1, 1); CP_COMMIT();
    ldchunk(2, 2); CP_COMMIT();

    #pragma unroll 1
    for (int it = 0; it < 24; it++) {
        CP_WAIT2();
        __syncthreads();
        const int pf = it + 3;
        if (pf < 24) ldchunk(pf, pf & 3);
        CP_COMMIT();
        compute(it & 3);
    }
    CP_WAITALL();

    if (z == domaxZ) {
        float mx = -3.402823466e38f;
        #pragma unroll
        for (int mt = 0; mt < 2; mt++)
            #pragma unroll
            for (int nt = 0; nt < 8; nt++)
                #pragma unroll
                for (int q = 0; q < 4; q++)
                    mx = fmaxf(mx, acc[mt][nt][q]);
        __syncthreads();
        mx = blockMax256(mx, (float*)smemBuf);
        if (tid == 0)
            atomicMax((unsigned*)(g_f + F_KMAX) + (m0 >> 11), ord_enc(mx));
    }

    // epilogue
    #pragma unroll
    for (int mt = 0; mt < 2; mt++) {
        #pragma unroll
        for (int hf = 0; hf < 2; hf++) {
            const int m = m0 + warp_m + mt * 16 + (lane >> 2) + hf * 8;
            float invd = 1.0f;
            if (epi == 3) invd = 1.0f / den[m];
            const int l = m & (L_SEQ - 1);
            #pragma unroll
            for (int nt = 0; nt < 8; nt++) {
                const int n = n0 + warp_n + nt * 8 + (lane & 3) * 2;
                float v0 = acc[mt][nt][hf * 2 + 0];
                float v1 = acc[mt][nt][hf * 2 + 1];
                if (epi == 1 || epi == 2) { v0 += bias[n]; v1 += bias[n + 1]; }
                if (epi == 2) {
                    const float sn = pos[(long)l * DMODEL + n];
                    const float cs = pos[(long)l * DMODEL + n + 1];
                    const float q0 = v0 * cs - v1 * sn;
                    const float q1 = v1 * cs + v0 * sn;
                    v0 = q0 * 0.25f; v1 = q1 * 0.25f;
                }
                if (epi == 3) { v0 *= invd; v1 *= invd; }
                if (Cf)
                    *(float2*)&Cf[(long)m * 256 + n] = make_float2(v0, v1);
                if (Ch) {
                    __nv_bfloat16 h0 = __float2bfloat16(v0);
                    __nv_bfloat16 h1 = __float2bfloat16(v1);
                    float l0 = v0 - __bfloat162float(h0);
                    float l1 = v1 - __bfloat162float(h1);
                    unsigned hp = ((unsigned)__bfloat16_as_ushort(h1) << 16)
                                | __bfloat16_as_ushort(h0);
                    unsigned lp = ((unsigned)__bfloat16_as_ushort(__float2bfloat16(l1)) << 16)
                                | __bfloat16_as_ushort(__float2bfloat16(l0));
                    *(unsigned*)&Ch[(long)m * 256 + n] = hp;
                    *(unsigned*)&Cl[(long)m * 256 + n] = lp;
                }
            }
        }
    }
}

// ===========================================================================
// TN GEMM (kvs), K-chunk 32, 4-stage cp.async (dynamic smem 69632B).
//   C[M,N] = (Ah+Al)^T @ (Bh+Bl); A [K,M], B [K,N], ldmatrix .trans.
//   Split-K: z = bz*8+sp, 256 K-rows/split; 24 chunks; f32 out.
// ===========================================================================
__global__ __launch_bounds__(256, 2)
void mma_tn(const __nv_bfloat16* __restrict__ Ah, const __nv_bfloat16* __restrict__ Al,
            const __nv_bfloat16* __restrict__ Bh, const __nv_bfloat16* __restrict__ Bl,
            float* __restrict__ Cf,
            long sAb, long sAs, long sBb, long sBs, long sCb, long sCs)
{
    extern __shared__ __align__(16) char smemBuf[];
    // stage = 32 rows x 272B x 2 = 17408B; 4 stages

    const int tid  = threadIdx.x;
    const int wid  = tid >> 5;
    const int lane = tid & 31;
    const int warp_m = (wid >> 1) * 32;
    const int warp_n = (wid & 1) * 64;

    const int z  = blockIdx.z;
    const int bz = z >> 3, sp = z & 7;
    const long aoff = (long)bz * sAb + (long)sp * sAs;
    const long boff = (long)bz * sBb + (long)sp * sBs;
    Cf += (long)bz * sCb + (long)sp * sCs;

    const int m0 = blockIdx.y * 128;
    const int n0 = blockIdx.x * 128;
    const uint32_t sbase = smem_u32(smemBuf);

    // load geometry: 32 rows x 8 threads/row, 32B per thread
    const int lrow = tid >> 3;            // 0..31 (K row)
    const int lcol = (tid & 7) * 16;      // element col (32B chunks)
    const __nv_bfloat16* aH = Ah + aoff + (long)lrow * 256 + m0 + lcol;
    const __nv_bfloat16* aL = Al + aoff + (long)lrow * 256 + m0 + lcol;
    const __nv_bfloat16* bH = Bh + boff + (long)lrow * 256 + n0 + lcol;
    const __nv_bfloat16* bL = Bl + boff + (long)lrow * 256 + n0 + lcol;
    const uint32_t dstA = sbase + lrow * 272 + (tid & 7) * 32;
    const uint32_t dstB = dstA + 8704;

    auto ldchunk = [&](int ck, int slot) {
        const int pass = ck >> 3;
        const long kk = (long)(ck & 7) * 32 * 256;
        const __nv_bfloat16* Ap = ((pass == 2) ? aL : aH) + kk;
        const __nv_bfloat16* Bq = ((pass == 1) ? bL : bH) + kk;
        const uint32_t so = slot * 17408;
        cp16(dstA + so,      Ap);
        cp16(dstA + so + 16, Ap + 8);
        cp16(dstB + so,      Bq);
        cp16(dstB + so + 16, Bq + 8);
    };

    const uint32_t aoffl = ((lane & 7) + ((lane >> 4) & 1) * 8) * 272
                         + (warp_m + ((lane >> 3) & 1) * 8) * 2;
    const uint32_t boffl = ((lane & 7) + ((lane >> 3) & 1) * 8) * 272
                         + (warp_n + ((lane >> 4) & 1) * 8) * 2;

    float acc[2][8][4] = {};

    auto compute = [&](int slot) {
        const uint32_t bA = sbase + slot * 17408;
        const uint32_t bB = bA + 8704;
        #pragma unroll
        for (int k16 = 0; k16 < 2; k16++) {
            uint32_t a[2][4];
            #pragma unroll
            for (int mt = 0; mt < 2; mt++)
                ldsm_x4_t(a[mt][0], a[mt][1], a[mt][2], a[mt][3],
                          bA + aoffl + k16 * 16 * 272 + mt * 16 * 2);
            uint32_t b[4][4];
            #pragma unroll
            for (int nt2 = 0; nt2 < 4; nt2++)
                ldsm_x4_t(b[nt2][0], b[nt2][1], b[nt2][2], b[nt2][3],
                          bB + boffl + k16 * 16 * 272 + nt2 * 16 * 2);
            #pragma unroll
            for (int mt = 0; mt < 2; mt++)
                #pragma unroll
                for (int nt = 0; nt < 8; nt++)
                    mma16816(acc[mt][nt], a[mt], &b[nt >> 1][(nt & 1) * 2]);
        }
    };

    ldchunk(0, 0); CP_COMMIT();
    ldchunk(1, 1); CP_COMMIT();
    ldchunk(2, 2); CP_COMMIT();

    #pragma unroll 1
    for (int it = 0; it < 24; it++) {
        CP_WAIT2();
        __syncthreads();
        const int pf = it + 3;
        if (pf < 24) ldchunk(pf, pf & 3);
        CP_COMMIT();
        compute(it & 3);
    }
    CP_WAITALL();

    #pragma unroll
    for (int mt = 0; mt < 2; mt++)
        #pragma unroll
        for (int hf = 0; hf < 2; hf++) {
            const int m = m0 + warp_m + mt * 16 + (lane >> 2) + hf * 8;
            #pragma unroll
            for (int nt = 0; nt < 8; nt++) {
                const int n = n0 + warp_n + nt * 8 + (lane & 3) * 2;
                *(float2*)&Cf[(long)m * 256 + n] =
                    make_float2(acc[mt][nt][hf * 2], acc[mt][nt][hf * 2 + 1]);
            }
        }
}

// ===========================================================================
// Elementwise kernels
// ===========================================================================
__global__ void clear_kernel() {
    if (threadIdx.x < BATCH)
        ((unsigned*)(g_f + F_KMAX))[threadIdx.x] = 0u;
}

__global__ __launch_bounds__(256)
void conv4(const float* __restrict__ in0, const float* __restrict__ in1,
           const float* __restrict__ in2, __nv_bfloat16* __restrict__ outBase,
           long stride, long n4) {
    const float* in = (blockIdx.z == 0) ? in0 : (blockIdx.z == 1) ? in1 : in2;
    __nv_bfloat16* h = outBase + (long)blockIdx.z * 2 * stride;
    __nv_bfloat16* l = h + stride;
    long i = (long)blockIdx.x * 256 + threadIdx.x;
    if (i < n4) {
        float4 x = ((const float4*)in)[i];
        float xs[4] = {x.x, x.y, x.z, x.w};
        unsigned short hh[4], ll[4];
        #pragma unroll
        for (int j = 0; j < 4; j++) {
            __nv_bfloat16 hi = __float2bfloat16(xs[j]);
            hh[j] = __bfloat16_as_ushort(hi);
            ll[j] = __bfloat16_as_ushort(__float2bfloat16(xs[j] - __bfloat162float(hi)));
        }
        ((uint2*)h)[i] = make_uint2((unsigned)hh[0] | ((unsigned)hh[1] << 16),
                                    (unsigned)hh[2] | ((unsigned)hh[3] << 16));
        ((uint2*)l)[i] = make_uint2((unsigned)ll[0] | ((unsigned)ll[1] << 16),
                                    (unsigned)ll[2] | ((unsigned)ll[3] << 16));
    }
}

__global__ __launch_bounds__(256)
void tconvW(const float* __restrict__ w0, const float* __restrict__ w1,
            const float* __restrict__ w2, const float* __restrict__ w3,
            __nv_bfloat16* __restrict__ outBase) {
    __shared__ float t[32][33];
    const int zz = blockIdx.z;
    const float* in = (zz == 0) ? w0 : (zz == 1) ? w1 : (zz == 2) ? w2 : w3;
    __nv_bfloat16* oh = outBase + (long)zz * 2 * SZW;
    __nv_bfloat16* ol = oh + SZW;
    const int r0 = blockIdx.x * 32, c0 = blockIdx.y * 32;
    const int tx = threadIdx.x, ty = threadIdx.y;
    #pragma unroll
    for (int d = 0; d < 4; d++)
        t[ty + 8 * d][tx] = in[(long)(r0 + ty + 8 * d) * 256 + c0 + tx];
    __syncthreads();
    #pragma unroll
    for (int d = 0; d < 4; d++) {
        const int cc = c0 + ty + 8 * d;
        float x = t[tx][ty + 8 * d];
        __nv_bfloat16 hi = __float2bfloat16(x);
        long o = (long)cc * 256 + r0 + tx;
        oh[o] = hi;
        ol[o] = __float2bfloat16(x - __bfloat162float(hi));
    }
}

__global__ __launch_bounds__(256)
void kvsred() {
    __shared__ float t[32][33];
    const int b = blockIdx.z;
    const int m0 = blockIdx.x * 32, d0 = blockIdx.y * 32;
    const int tx = threadIdx.x, ty = threadIdx.y;
    const float* p = g_f + F_PART + (long)b * 8 * SZW;
    #pragma unroll
    for (int dd = 0; dd < 4; dd++) {
        const int m = m0 + ty + 8 * dd;
        float s = 0.f;
        #pragma unroll
        for (int spl = 0; spl < 8; spl++)
            s += p[(long)spl * SZW + (long)m * 256 + d0 + tx];
        t[ty + 8 * dd][tx] = s;
    }
    __syncthreads();
    #pragma unroll
    for (int dd = 0; dd < 4; dd++) {
        const int d = d0 + ty + 8 * dd;
        float x = t[tx][ty + 8 * dd];
        __nv_bfloat16 hi = __float2bfloat16(x);
        long o = (long)b * SZW + (long)d * 256 + m0 + tx;
        g_b[B_KVSTH + o] = hi;
        g_b[B_KVSTL + o] = __float2bfloat16(x - __bfloat162float(hi));
    }
}

__global__ __launch_bounds__(256) void kp_kernel() {
    const int row = blockIdx.x;
    const int b   = row >> 11;
    const int t   = threadIdx.x;
    const long base = (long)row * MFEAT;
    const float x = __bfloat162float(g_b[B_KSH + base + t])
                  + __bfloat162float(g_b[B_KSL + base + t]);
    const float xp = g_f[F_XK + base + t];
    __shared__ float sm8[8];
    const float diag = 0.5f * blockSum256(x * x, sm8);
    const float mx = ord_dec(((const unsigned*)(g_f + F_KMAX))[b]);
    const float kp = 0.0625f * (expf(xp - diag - mx) + 1e-6f);
    __nv_bfloat16 hi = __float2bfloat16(kp);
    g_b[B_KPH + base + t] = hi;
    g_b[B_KPL + base + t] = __float2bfloat16(kp - __bfloat162float(hi));
}

// ksum partials: 64 chunks of 32 rows per batch (grid (64, BATCH))
__global__ __launch_bounds__(256) void ksump_kernel() {
    const int b = blockIdx.y, chunk = blockIdx.x, m = threadIdx.x;
    const long baseh = B_KPH + (long)b * L_SEQ * MFEAT;
    const long basel = B_KPL + (long)b * L_SEQ * MFEAT;
    float s = 0.f;
    const int r0 = chunk * 32;
    #pragma unroll 4
    for (int r = 0; r < 32; r++) {
        const long o = (long)(r0 + r) * MFEAT + m;
        s += __bfloat162float(g_b[baseh + o]) + __bfloat162float(g_b[basel + o]);
    }
    g_f[F_KSUMP + ((long)b * KCH + chunk) * MFEAT + m] = s;
}

__global__ __launch_bounds__(256) void qpden_kernel() {
    const int row = blockIdx.x;
    const int b   = row >> 11;
    const int t   = threadIdx.x;
    const long base = (long)row * MFEAT;
    const float x = __bfloat162float(g_b[B_QSH + base + t])
                  + __bfloat162float(g_b[B_QSL + base + t]);
    const float xp = g_f[F_XQ + base + t];
    __shared__ float sm8[8];
    const float diag = 0.5f * blockSum256(x * x, sm8);
    const float mx   = blockMax256(xp, sm8);
    const float qp = 0.0625f * (expf(xp - diag - mx) + 1e-6f);
    __nv_bfloat16 hi = __float2bfloat16(qp);
    g_b[B_QPH + base + t] = hi;
    g_b[B_QPL + base + t] = __float2bfloat16(qp - __bfloat162float(hi));
    float ks = 0.f;
    #pragma unroll
    for (int c = 0; c < KCH; c++)
        ks += g_f[F_KSUMP + ((long)b * KCH + c) * MFEAT + t];
    const float den = blockSum256(qp * ks, sm8);
    if (t == 0) g_f[F_DEN + row] = den;
}

// ===========================================================================
// launch
// ===========================================================================
extern "C" void kernel_launch(void* const* d_in, const int* in_sizes, int n_in,
                              void* d_out, int out_size)
{
    const float* query = (const float*)d_in[0];
    const float* key   = (const float*)d_in[1];
    const float* value = (const float*)d_in[2];
    const float* Wq = (const float*)d_in[4];
    const float* bq = (const float*)d_in[5];
    const float* Wk = (const float*)d_in[6];
    const float* bk = (const float*)d_in[7];
    const float* Wv = (const float*)d_in[8];
    const float* bv = (const float*)d_in[9];
    const float* Wo = (const float*)d_in[10];
    const float* bo = (const float*)d_in[11];
    const float* proj = (const float*)d_in[12];
    const float* pos  = (const float*)d_in[13];
    float* out = (float*)d_out;

    void* fp = nullptr; cudaGetSymbolAddress(&fp, g_f);
    void* bp = nullptr; cudaGetSymbolAddress(&bp, g_b);
    float* F = (float*)fp;
    __nv_bfloat16* Bp = (__nv_bfloat16*)bp;

    static bool attrDone = false;
    if (!attrDone) {
        cudaFuncSetAttribute(mma_nt, cudaFuncAttributeMaxDynamicSharedMemorySize, 81920);
        cudaFuncSetAttribute(mma_tn, cudaFuncAttributeMaxDynamicSharedMemorySize, 69632);
        attrDone = true;
    }
    const int SM_NT = 81920, SM_TN = 69632;

    // 1: clear, 2: conv4 inputs, 3: weights, 4: qkv GEMM (profiled slot)
    clear_kernel<<<1, 32>>>();
    conv4<<<dim3((unsigned)(SZB / 1024), 1, 3), 256>>>(query, key, value,
                                                       Bp + B_QINH, SZB, SZB / 4);
    dim3 tb(32, 8);
    tconvW<<<dim3(8, 8, 4), tb>>>(Wq, Wk, Wv, Wo, Bp + B_WQTH);

    // merged q/k/v projections: z=0,1 rotary+bias, z=2 bias (epiMode=4)
    mma_nt<<<dim3(2, 64, 3), 256, SM_NT>>>(
        Bp + B_QINH, Bp + B_QINL, Bp + B_WQTH, Bp + B_WQTL,
        nullptr, Bp + B_QSH, Bp + B_QSL,
        bq, bk, bv, nullptr, pos,
        2 * SZB, 2 * SZW, 2 * SZB, 0, 4, -1);

    conv4<<<dim3(64, 1, 1), 256>>>(proj, proj, proj, Bp + B_PRJH, SZW, SZW / 4);

    // merged xq/xk: z=0 -> XQ, z=1 -> XK (+per-batch max)
    mma_nt<<<dim3(2, 64, 2), 256, SM_NT>>>(
        Bp + B_QSH, Bp + B_QSL, Bp + B_PRJH, Bp + B_PRJL,
        F + F_XQ, nullptr, nullptr,
        nullptr, nullptr, nullptr, nullptr, nullptr,
        2 * SZB, 0, SZB, 0, 0, 1);

    kp_kernel<<<NROWS, 256>>>();
    ksump_kernel<<<dim3(KCH, BATCH), 256>>>();
    qpden_kernel<<<NROWS, 256>>>();

    // kvs[b] = kp[b]^T @ v[b] (TN, split-K 8)
    mma_tn<<<dim3(2, 2, 32), 256, SM_TN>>>(Bp + B_KPH, Bp + B_KPL, Bp + B_VH, Bp + B_VL,
        F + F_PART,
        (long)L_SEQ * MFEAT, (long)256 * MFEAT,
        (long)L_SEQ * 256,  (long)256 * 256,
        (long)8 * SZW, SZW);
    kvsred<<<dim3(8, 8, BATCH), tb>>>();

    // ctx = (qp @ kvs) / den (batched z = b)
    mma_nt<<<dim3(2, 16, BATCH), 256, SM_NT>>>(
        Bp + B_QPH, Bp + B_QPL, Bp + B_KVSTH, Bp + B_KVSTL,
        nullptr, Bp + B_CTXH, Bp + B_CTXL,
        nullptr, nullptr, nullptr, F + F_DEN, nullptr,
        (long)L_SEQ * 256, SZW, (long)L_SEQ * 256, L_SEQ,
        3, -1);

    // out = ctx @ Wo + bo
    mma_nt<<<dim3(2, 64, 1), 256, SM_NT>>>(
        Bp + B_CTXH, Bp + B_CTXL, Bp + B_WOTH, Bp + B_WOTL,
        out, nullptr, nullptr,
        bo, bo, bo, nullptr, nullptr,
        0, 0, 0, 0, 1, -1);
}